// round 3
// baseline (speedup 1.0000x reference)
#include <cuda_runtime.h>
#include <math.h>

#define NB 64
#define TIN 1000
#define CIN 4
#define FEAT 320
#define KW 26
#define POOLW 13
#define TPOOL 75
#define HU 320
#define H3 960
#define FLATN 48000
#define ND1 2000
#define ND2 301
#define KSPLIT 8
#define KSEG (FLATN / KSPLIT)

#define GRU_BLOCKS 128
#define GRU_THREADS 320
#define GRU_SMEM ((HU*NB + 15*HU) * 4)

__device__ float g_pooled[NB*TPOOL*FEAT];
__device__ float g_xp[2][TPOOL*H3*NB];
__device__ float g_y[FLATN*NB];
__device__ float g_h[2][2][HU*NB];
__device__ float g_part[KSPLIT][NB*ND1];
__device__ float g_hidden[NB*ND1];
__device__ unsigned g_cnt;
__device__ unsigned g_gen;

__device__ __forceinline__ float sigf(float x) { return 1.0f / (1.0f + __expf(-x)); }

__global__ void __launch_bounds__(256) conv_kernel(const float* __restrict__ in,
                                                   const float* __restrict__ cw,
                                                   const float* __restrict__ cb)
{
    __shared__ float xs[CIN*TIN];
    __shared__ float ws[KW*CIN*64];
    int b = blockIdx.y, f0 = blockIdx.x * 64, tid = threadIdx.x;

    for (int i = tid; i < CIN*TIN; i += 256)
        xs[(i & 3)*TIN + (i >> 2)] = in[b*TIN*CIN + i];
    for (int i = tid; i < KW*CIN*64; i += 256)
        ws[i] = cw[(i >> 6)*FEAT + f0 + (i & 63)];
    __syncthreads();

    int fl = tid & 31, tg = tid >> 5;
    float ba = cb[f0 + fl], bb = cb[f0 + 32 + fl];

    for (int tp = tg; tp < TPOOL; tp += 8) {
        int t0 = tp * POOLW;
        float aa[POOLW], ab[POOLW];
        #pragma unroll
        for (int p = 0; p < POOLW; p++) { aa[p] = ba; ab[p] = bb; }
        #pragma unroll 1
        for (int k = 0; k < KW; k++) {
            #pragma unroll
            for (int c = 0; c < CIN; c++) {
                float wa = ws[(k*CIN + c)*64 + fl];
                float wb = ws[(k*CIN + c)*64 + 32 + fl];
                const float* xp = &xs[c*TIN + t0 + k];
                #pragma unroll
                for (int p = 0; p < POOLW; p++) {
                    float xv = xp[p];
                    aa[p] = fmaf(xv, wa, aa[p]);
                    ab[p] = fmaf(xv, wb, ab[p]);
                }
            }
        }
        float ma = aa[0], mb = ab[0];
        #pragma unroll
        for (int p = 1; p < POOLW; p++) { ma = fmaxf(ma, aa[p]); mb = fmaxf(mb, ab[p]); }
        g_pooled[(b*TPOOL + tp)*FEAT + f0 + fl]      = fmaxf(ma, 0.f);
        g_pooled[(b*TPOOL + tp)*FEAT + f0 + 32 + fl] = fmaxf(mb, 0.f);
    }
}

__global__ void __launch_bounds__(256) xproj_kernel(const float* __restrict__ Bk,
                                                    const float* __restrict__ bias,
                                                    int dir)
{
    __shared__ __align__(16) float As[16][64];
    __shared__ __align__(16) float Bs[16][64];
    int m0 = blockIdx.x * 64, n0 = blockIdx.y * 64, tid = threadIdx.x;

    float acc[4][4] = {};
    int tm = (tid & 15) * 4, tn = (tid >> 4) * 4;
    int la_m = tid & 63, la_k = (tid >> 6) * 4;
    int lb_k = tid >> 4, lb_n = (tid & 15) * 4;

    for (int k0 = 0; k0 < FEAT; k0 += 16) {
        float4 av = *(const float4*)&g_pooled[(m0 + la_m)*FEAT + k0 + la_k];
        As[la_k+0][la_m] = av.x; As[la_k+1][la_m] = av.y;
        As[la_k+2][la_m] = av.z; As[la_k+3][la_m] = av.w;
        *(float4*)&Bs[lb_k][lb_n] = *(const float4*)&Bk[(k0 + lb_k)*H3 + n0 + lb_n];
        __syncthreads();
        #pragma unroll
        for (int kk = 0; kk < 16; kk++) {
            float4 a = *(const float4*)&As[kk][tm];
            float4 q = *(const float4*)&Bs[kk][tn];
            float ar[4] = {a.x,a.y,a.z,a.w}, qr[4] = {q.x,q.y,q.z,q.w};
            #pragma unroll
            for (int i = 0; i < 4; i++)
                #pragma unroll
                for (int j = 0; j < 4; j++)
                    acc[i][j] = fmaf(ar[i], qr[j], acc[i][j]);
        }
        __syncthreads();
    }
    float* xp = g_xp[dir];
    #pragma unroll
    for (int i = 0; i < 4; i++) {
        int m = m0 + tm + i, bb = m / TPOOL, t = m - bb*TPOOL;
        #pragma unroll
        for (int j = 0; j < 4; j++) {
            int n = n0 + tn + j;
            xp[(t*H3 + n)*NB + bb] = acc[i][j] + bias[n];
        }
    }
}

__device__ __forceinline__ void grid_sync_()
{
    __threadfence();
    __syncthreads();
    if (threadIdx.x == 0) {
        unsigned gen = *((volatile unsigned*)&g_gen);
        if (atomicAdd(&g_cnt, 1u) == gridDim.x - 1u) {
            g_cnt = 0u;
            __threadfence();
            atomicAdd(&g_gen, 1u);
        } else {
            while (*((volatile unsigned*)&g_gen) == gen) { }
        }
    }
    __syncthreads();
}

__global__ void __launch_bounds__(GRU_THREADS, 1) gru_kernel(
    const float* __restrict__ rk_fw, const float* __restrict__ rk_bw,
    const float* __restrict__ b_fw,  const float* __restrict__ b_bw)
{
    extern __shared__ float sm[];
    float* hs  = sm;                 /* [HU][NB] */
    float* rks = sm + HU*NB;         /* [15][HU] col = gate*5+jj */

    int bx = blockIdx.x, dir = bx >> 6, jb = bx & 63, j0 = jb * 5;
    const float* rk = dir ? rk_bw : rk_fw;
    const float* br = (dir ? b_bw : b_fw) + H3;
    const float* xp = g_xp[dir];
    int tid = threadIdx.x;

    for (int i = tid; i < 15*HU; i += GRU_THREADS) {
        int col = i / HU, k = i - col*HU;
        int g = col / 5, jj = col % 5;
        rks[col*HU + k] = rk[k*H3 + g*HU + j0 + jj];
    }
    __syncthreads();

    int b = tid & 63, jj = tid >> 6, jg = j0 + jj;
    const float4* pz = (const float4*)&rks[(0*5 + jj)*HU];
    const float4* pr = (const float4*)&rks[(1*5 + jj)*HU];
    const float4* ph = (const float4*)&rks[(2*5 + jj)*HU];
    float brz = br[jg], brr = br[HU + jg], brh = br[2*HU + jg];
    float* h0p = g_h[dir][0];
    float* h1p = g_h[dir][1];

    for (int s = 0; s < TPOOL; s++) {
        int tt = dir ? (TPOOL - 1 - s) : s;
        const float* mx = &xp[tt*H3*NB + b];
        float mz = mx[jg*NB], mr = mx[(HU + jg)*NB], mh = mx[(2*HU + jg)*NB];

        float az = 0.f, ar2 = 0.f, ah = 0.f, hold = 0.f;
        if (s > 0) {
            const float4* hr = (const float4*)((s & 1) ? h1p : h0p);
            float4* hs4 = (float4*)hs;
            for (int i = tid; i < HU*NB/4; i += GRU_THREADS)
                hs4[i] = __ldcg(&hr[i]);
            __syncthreads();
            #pragma unroll 4
            for (int k = 0; k < HU; k += 4) {
                float v0 = hs[(k+0)*NB + b], v1 = hs[(k+1)*NB + b];
                float v2 = hs[(k+2)*NB + b], v3 = hs[(k+3)*NB + b];
                float4 wz = pz[k >> 2], wr = pr[k >> 2], wh = ph[k >> 2];
                az  = fmaf(v0,wz.x,az);  az  = fmaf(v1,wz.y,az);
                az  = fmaf(v2,wz.z,az);  az  = fmaf(v3,wz.w,az);
                ar2 = fmaf(v0,wr.x,ar2); ar2 = fmaf(v1,wr.y,ar2);
                ar2 = fmaf(v2,wr.z,ar2); ar2 = fmaf(v3,wr.w,ar2);
                ah  = fmaf(v0,wh.x,ah);  ah  = fmaf(v1,wh.y,ah);
                ah  = fmaf(v2,wh.z,ah);  ah  = fmaf(v3,wh.w,ah);
            }
            hold = hs[jg*NB + b];
        }

        float z    = sigf(mz + az + brz);
        float r    = sigf(mr + ar2 + brr);
        float cand = tanhf(mh + r * (ah + brh));
        float hn   = z * hold + (1.f - z) * cand;

        float* hw = (s & 1) ? h0p : h1p;
        hw[jg*NB + b] = hn;
        g_y[((tt*2 + dir)*HU + jg)*NB + b] = hn;

        if (s < TPOOL - 1) grid_sync_();
    }
}

__global__ void __launch_bounds__(256) dense1_kernel(const float* __restrict__ W)
{
    __shared__ __align__(16) float As[16][64];
    __shared__ __align__(16) float Bs[16][64];
    int n0 = blockIdx.x * 64, ks = blockIdx.y, kbeg = ks * KSEG, tid = threadIdx.x;

    float acc[4][4] = {};
    int tm = (tid & 15) * 4, tn = (tid >> 4) * 4;
    int lk = tid >> 4, lm = (tid & 15) * 4, ln = (tid & 15) * 4;
    bool bvalid = (n0 + ln) < ND1;

    for (int k0 = kbeg; k0 < kbeg + KSEG; k0 += 16) {
        *(float4*)&As[lk][lm] = *(const float4*)&g_y[(k0 + lk)*NB + lm];
        float4 bv = make_float4(0.f,0.f,0.f,0.f);
        if (bvalid) bv = *(const float4*)&W[(size_t)(k0 + lk)*ND1 + n0 + ln];
        *(float4*)&Bs[lk][ln] = bv;
        __syncthreads();
        #pragma unroll
        for (int kk = 0; kk < 16; kk++) {
            float4 a = *(const float4*)&As[kk][tm];
            float4 q = *(const float4*)&Bs[kk][tn];
            float ar[4] = {a.x,a.y,a.z,a.w}, qr[4] = {q.x,q.y,q.z,q.w};
            #pragma unroll
            for (int i = 0; i < 4; i++)
                #pragma unroll
                for (int j = 0; j < 4; j++)
                    acc[i][j] = fmaf(ar[i], qr[j], acc[i][j]);
        }
        __syncthreads();
    }
    float* dst = g_part[ks];
    #pragma unroll
    for (int i = 0; i < 4; i++) {
        int m = tm + i;
        #pragma unroll
        for (int j = 0; j < 4; j++) {
            int n = n0 + tn + j;
            if (n < ND1) dst[m*ND1 + n] = acc[i][j];
        }
    }
}

__global__ void __launch_bounds__(256) reduce1_kernel(const float* __restrict__ b1)
{
    int i = blockIdx.x * 256 + threadIdx.x;
    if (i >= NB*ND1) return;
    int n = i % ND1;
    float s = b1[n];
    #pragma unroll
    for (int p = 0; p < KSPLIT; p++) s += g_part[p][i];
    g_hidden[i] = fmaxf(s, 0.f);
}

__global__ void __launch_bounds__(64) dense2_kernel(const float* __restrict__ w2,
                                                    const float* __restrict__ b2,
                                                    float* __restrict__ out)
{
    int n = blockIdx.x, m = threadIdx.x;
    const float4* hrow = (const float4*)&g_hidden[m*ND1];
    float acc = 0.f;
    #pragma unroll 4
    for (int k = 0; k < ND1; k += 4) {
        float4 hv = hrow[k >> 2];
        acc = fmaf(hv.x, w2[(k+0)*ND2 + n], acc);
        acc = fmaf(hv.y, w2[(k+1)*ND2 + n], acc);
        acc = fmaf(hv.z, w2[(k+2)*ND2 + n], acc);
        acc = fmaf(hv.w, w2[(k+3)*ND2 + n], acc);
    }
    out[m*ND2 + n] = sigf(acc + b2[n]);
}

extern "C" void kernel_launch(void* const* d_in, const int* in_sizes, int n_in,
                              void* d_out, int out_size)
{
    const float* inputs = (const float*)d_in[0];
    const float* conv_w = (const float*)d_in[1];
    const float* conv_b = (const float*)d_in[2];
    const float* fw_k   = (const float*)d_in[3];
    const float* fw_rk  = (const float*)d_in[4];
    const float* fw_b   = (const float*)d_in[5];
    const float* bw_k   = (const float*)d_in[6];
    const float* bw_rk  = (const float*)d_in[7];
    const float* bw_b   = (const float*)d_in[8];
    const float* w1     = (const float*)d_in[9];
    const float* b1     = (const float*)d_in[10];
    const float* w2     = (const float*)d_in[11];
    const float* b2     = (const float*)d_in[12];
    float* out = (float*)d_out;

    cudaFuncSetAttribute(gru_kernel, cudaFuncAttributeMaxDynamicSharedMemorySize, GRU_SMEM);

    conv_kernel<<<dim3(FEAT/64, NB), 256>>>(inputs, conv_w, conv_b);
    xproj_kernel<<<dim3((NB*TPOOL)/64, H3/64), 256>>>(fw_k, fw_b, 0);
    xproj_kernel<<<dim3((NB*TPOOL)/64, H3/64), 256>>>(bw_k, bw_b, 1);
    gru_kernel<<<GRU_BLOCKS, GRU_THREADS, GRU_SMEM>>>(fw_rk, bw_rk, fw_b, bw_b);
    dense1_kernel<<<dim3((ND1 + 63)/64, KSPLIT), 256>>>(w1);
    reduce1_kernel<<<(NB*ND1 + 255)/256, 256>>>(b1);
    dense2_kernel<<<ND2, 64>>>(w2, b2, out);
}

// round 4
// speedup vs baseline: 1.3838x; 1.3838x over previous
#include <cuda_runtime.h>
#include <math.h>

#define NB 64
#define TIN 1000
#define CIN 4
#define FEAT 320
#define KW 26
#define POOLW 13
#define TPOOL 75
#define HU 320
#define H3 960
#define FLATN 48000
#define ND1 2000
#define ND2 301
#define KSPLIT 8
#define KSEG (FLATN / KSPLIT)

#define GRU_BLOCKS 128
#define GRU_THREADS 320
#define GRU_SMEM ((HU*NB + 15*HU) * 4)

__device__ float g_pooled[NB*TPOOL*FEAT];
__device__ float g_xp[2][TPOOL*H3*NB];
__device__ float g_y[FLATN*NB];
__device__ float g_h[2][2][HU*NB];
__device__ float g_part[KSPLIT][NB*ND1];
__device__ float g_hidden[NB*ND1];
__device__ unsigned g_cnt;
__device__ unsigned g_gen;

__device__ __forceinline__ float sigf(float x) { return 1.0f / (1.0f + __expf(-x)); }

/* ---------------- tensor-core helpers (tf32 m16n8k8) --------------------- */
__device__ __forceinline__ void cp16(const void* dst, const void* src) {
    unsigned d = (unsigned)__cvta_generic_to_shared(dst);
    asm volatile("cp.async.cg.shared.global [%0], [%1], 16;\n" :: "r"(d), "l"(src));
}
__device__ __forceinline__ void cpcommit() { asm volatile("cp.async.commit_group;\n" ::); }
__device__ __forceinline__ void cpwait1()  { asm volatile("cp.async.wait_group 1;\n" ::); }
__device__ __forceinline__ unsigned tf32r(float x) {
    unsigned r; asm("cvt.rna.tf32.f32 %0, %1;\n" : "=r"(r) : "f"(x)); return r;
}
__device__ __forceinline__ void mma8(float* c, const unsigned* a, const unsigned* b) {
    asm volatile(
        "mma.sync.aligned.m16n8k8.row.col.f32.tf32.tf32.f32 "
        "{%0,%1,%2,%3},{%4,%5,%6,%7},{%8,%9},{%0,%1,%2,%3};\n"
        : "+f"(c[0]), "+f"(c[1]), "+f"(c[2]), "+f"(c[3])
        : "r"(a[0]), "r"(a[1]), "r"(a[2]), "r"(a[3]), "r"(b[0]), "r"(b[1]));
}

/* ---------------- conv1d + relu + maxpool13 ------------------------------ */
__global__ void __launch_bounds__(256) conv_kernel(const float* __restrict__ in,
                                                   const float* __restrict__ cw,
                                                   const float* __restrict__ cb)
{
    __shared__ float xs[CIN*TIN];
    __shared__ float ws[KW*CIN*64];
    int b = blockIdx.y, f0 = blockIdx.x * 64, tid = threadIdx.x;

    for (int i = tid; i < CIN*TIN; i += 256)
        xs[(i & 3)*TIN + (i >> 2)] = in[b*TIN*CIN + i];
    for (int i = tid; i < KW*CIN*64; i += 256)
        ws[i] = cw[(i >> 6)*FEAT + f0 + (i & 63)];
    __syncthreads();

    int fl = tid & 31, tg = tid >> 5;
    float ba = cb[f0 + fl], bb = cb[f0 + 32 + fl];

    for (int tp = tg; tp < TPOOL; tp += 8) {
        int t0 = tp * POOLW;
        float aa[POOLW], ab[POOLW];
        #pragma unroll
        for (int p = 0; p < POOLW; p++) { aa[p] = ba; ab[p] = bb; }
        #pragma unroll 1
        for (int k = 0; k < KW; k++) {
            #pragma unroll
            for (int c = 0; c < CIN; c++) {
                float wa = ws[(k*CIN + c)*64 + fl];
                float wb = ws[(k*CIN + c)*64 + 32 + fl];
                const float* xp = &xs[c*TIN + t0 + k];
                #pragma unroll
                for (int p = 0; p < POOLW; p++) {
                    float xv = xp[p];
                    aa[p] = fmaf(xv, wa, aa[p]);
                    ab[p] = fmaf(xv, wb, ab[p]);
                }
            }
        }
        float ma = aa[0], mb = ab[0];
        #pragma unroll
        for (int p = 1; p < POOLW; p++) { ma = fmaxf(ma, aa[p]); mb = fmaxf(mb, ab[p]); }
        g_pooled[(b*TPOOL + tp)*FEAT + f0 + fl]      = fmaxf(ma, 0.f);
        g_pooled[(b*TPOOL + tp)*FEAT + f0 + 32 + fl] = fmaxf(mb, 0.f);
    }
}

/* ------- xproj via tf32 MMA: C(4800,960) = pooled(4800,320) @ K + bi ----- */
__global__ void __launch_bounds__(256) xproj_mma(const float* __restrict__ fwk,
                                                 const float* __restrict__ bwk,
                                                 const float* __restrict__ fwb,
                                                 const float* __restrict__ bwb)
{
    __shared__ __align__(16) float As[2][64][20];   /* [m][k], pad->20 */
    __shared__ __align__(16) float Ws[2][16][72];   /* [k][n], pad->72 */
    int m0 = blockIdx.x * 64, n0 = blockIdx.y * 64, dir = blockIdx.z;
    const float* Bk   = dir ? bwk : fwk;
    const float* bias = dir ? bwb : fwb;
    float* xp = g_xp[dir];

    int tid = threadIdx.x, warp = tid >> 5, lane = tid & 31;
    int g = lane >> 2, tg = lane & 3;
    int wm = (warp >> 2) * 32, wn = (warp & 3) * 16;
    int a_m = tid >> 2, a_k = (tid & 3) * 4;
    int w_k = tid >> 4, w_n = (tid & 15) * 4;

    float c[2][2][4] = {};

    /* prefetch chunk 0 */
    cp16(&As[0][a_m][a_k], &g_pooled[(m0 + a_m)*FEAT + a_k]);
    cp16(&Ws[0][w_k][w_n], &Bk[w_k*H3 + n0 + w_n]);
    cpcommit();

    const int NIT = FEAT / 16;   /* 20 */
    for (int it = 0; it < NIT; it++) {
        int nb = (it + 1) & 1;
        if (it + 1 < NIT) {
            int k0 = (it + 1) * 16;
            cp16(&As[nb][a_m][a_k], &g_pooled[(m0 + a_m)*FEAT + k0 + a_k]);
            cp16(&Ws[nb][w_k][w_n], &Bk[(k0 + w_k)*H3 + n0 + w_n]);
        }
        cpcommit();
        cpwait1();
        __syncthreads();
        int bf = it & 1;
        #pragma unroll
        for (int kh = 0; kh < 2; kh++) {
            int kk = kh * 8;
            unsigned a[2][4], b[2][2];
            #pragma unroll
            for (int mf = 0; mf < 2; mf++) {
                int m = wm + mf*16 + g;
                a[mf][0] = tf32r(As[bf][m    ][kk + tg]);
                a[mf][1] = tf32r(As[bf][m + 8][kk + tg]);
                a[mf][2] = tf32r(As[bf][m    ][kk + tg + 4]);
                a[mf][3] = tf32r(As[bf][m + 8][kk + tg + 4]);
            }
            #pragma unroll
            for (int nf = 0; nf < 2; nf++) {
                int n = wn + nf*8 + g;
                b[nf][0] = tf32r(Ws[bf][kk + tg    ][n]);
                b[nf][1] = tf32r(Ws[bf][kk + tg + 4][n]);
            }
            #pragma unroll
            for (int mf = 0; mf < 2; mf++)
                #pragma unroll
                for (int nf = 0; nf < 2; nf++)
                    mma8(c[mf][nf], a[mf], b[nf]);
        }
        __syncthreads();
    }

    #pragma unroll
    for (int mf = 0; mf < 2; mf++) {
        #pragma unroll
        for (int nf = 0; nf < 2; nf++) {
            int col = n0 + wn + nf*8 + tg*2;
            float bv0 = bias[col], bv1 = bias[col + 1];
            int r0 = m0 + wm + mf*16 + g;
            int b0 = r0 / TPOOL, t0 = r0 - b0*TPOOL;
            int r1 = r0 + 8;
            int b1 = r1 / TPOOL, t1 = r1 - b1*TPOOL;
            xp[(t0*H3 + col    )*NB + b0] = c[mf][nf][0] + bv0;
            xp[(t0*H3 + col + 1)*NB + b0] = c[mf][nf][1] + bv1;
            xp[(t1*H3 + col    )*NB + b1] = c[mf][nf][2] + bv0;
            xp[(t1*H3 + col + 1)*NB + b1] = c[mf][nf][3] + bv1;
        }
    }
}

/* ---------------- persistent bidirectional GRU --------------------------- */
__device__ __forceinline__ void grid_sync_()
{
    __threadfence();
    __syncthreads();
    if (threadIdx.x == 0) {
        unsigned gen = *((volatile unsigned*)&g_gen);
        if (atomicAdd(&g_cnt, 1u) == gridDim.x - 1u) {
            g_cnt = 0u;
            __threadfence();
            atomicAdd(&g_gen, 1u);
        } else {
            while (*((volatile unsigned*)&g_gen) == gen) { }
        }
    }
    __syncthreads();
}

__global__ void __launch_bounds__(GRU_THREADS, 1) gru_kernel(
    const float* __restrict__ rk_fw, const float* __restrict__ rk_bw,
    const float* __restrict__ b_fw,  const float* __restrict__ b_bw)
{
    extern __shared__ float sm[];
    float* hs  = sm;
    float* rks = sm + HU*NB;

    int bx = blockIdx.x, dir = bx >> 6, jb = bx & 63, j0 = jb * 5;
    const float* rk = dir ? rk_bw : rk_fw;
    const float* br = (dir ? b_bw : b_fw) + H3;
    const float* xp = g_xp[dir];
    int tid = threadIdx.x;

    for (int i = tid; i < 15*HU; i += GRU_THREADS) {
        int col = i / HU, k = i - col*HU;
        int g = col / 5, jj = col % 5;
        rks[col*HU + k] = rk[k*H3 + g*HU + j0 + jj];
    }
    __syncthreads();

    int b = tid & 63, jj = tid >> 6, jg = j0 + jj;
    const float4* pz = (const float4*)&rks[(0*5 + jj)*HU];
    const float4* pr = (const float4*)&rks[(1*5 + jj)*HU];
    const float4* ph = (const float4*)&rks[(2*5 + jj)*HU];
    float brz = br[jg], brr = br[HU + jg], brh = br[2*HU + jg];
    float* h0p = g_h[dir][0];
    float* h1p = g_h[dir][1];

    for (int s = 0; s < TPOOL; s++) {
        int tt = dir ? (TPOOL - 1 - s) : s;
        const float* mx = &xp[tt*H3*NB + b];
        float mz = mx[jg*NB], mr = mx[(HU + jg)*NB], mh = mx[(2*HU + jg)*NB];

        float az = 0.f, ar2 = 0.f, ah = 0.f, hold = 0.f;
        if (s > 0) {
            const float4* hr = (const float4*)((s & 1) ? h1p : h0p);
            float4* hs4 = (float4*)hs;
            for (int i = tid; i < HU*NB/4; i += GRU_THREADS)
                hs4[i] = __ldcg(&hr[i]);
            __syncthreads();
            #pragma unroll 4
            for (int k = 0; k < HU; k += 4) {
                float v0 = hs[(k+0)*NB + b], v1 = hs[(k+1)*NB + b];
                float v2 = hs[(k+2)*NB + b], v3 = hs[(k+3)*NB + b];
                float4 wz = pz[k >> 2], wr = pr[k >> 2], wh = ph[k >> 2];
                az  = fmaf(v0,wz.x,az);  az  = fmaf(v1,wz.y,az);
                az  = fmaf(v2,wz.z,az);  az  = fmaf(v3,wz.w,az);
                ar2 = fmaf(v0,wr.x,ar2); ar2 = fmaf(v1,wr.y,ar2);
                ar2 = fmaf(v2,wr.z,ar2); ar2 = fmaf(v3,wr.w,ar2);
                ah  = fmaf(v0,wh.x,ah);  ah  = fmaf(v1,wh.y,ah);
                ah  = fmaf(v2,wh.z,ah);  ah  = fmaf(v3,wh.w,ah);
            }
            hold = hs[jg*NB + b];
        }

        float z    = sigf(mz + az + brz);
        float r    = sigf(mr + ar2 + brr);
        float cand = tanhf(mh + r * (ah + brh));
        float hn   = z * hold + (1.f - z) * cand;

        float* hw = (s & 1) ? h0p : h1p;
        hw[jg*NB + b] = hn;
        g_y[((tt*2 + dir)*HU + jg)*NB + b] = hn;

        if (s < TPOOL - 1) grid_sync_();
    }
}

/* -------- dense1 via tf32 MMA: part(64,2000) = Y(64,48000) @ W1 ---------- */
__global__ void __launch_bounds__(256) dense1_mma(const float* __restrict__ W)
{
    __shared__ __align__(16) float As[2][16][72];    /* [k][m], pad->72  */
    __shared__ __align__(16) float Ws[2][16][136];   /* [k][n], pad->136 */
    int n0 = blockIdx.x * 128;
    int kbeg = blockIdx.y * KSEG;
    int tid = threadIdx.x, warp = tid >> 5, lane = tid & 31;
    int g = lane >> 2, tg = lane & 3;
    int wm = (warp >> 2) * 32, wn = (warp & 3) * 32;

    int a_k = tid >> 4, a_m = (tid & 15) * 4;
    int w_k = tid >> 5, w_n = (tid & 31) * 4;
    bool wok = (n0 + w_n) < ND1;

    if (!wok) {
        #pragma unroll
        for (int bf = 0; bf < 2; bf++) {
            *(float4*)&Ws[bf][w_k    ][w_n] = make_float4(0,0,0,0);
            *(float4*)&Ws[bf][w_k + 8][w_n] = make_float4(0,0,0,0);
        }
    }

    float c[2][4][4] = {};

    cp16(&As[0][a_k][a_m], &g_y[(kbeg + a_k)*NB + a_m]);
    if (wok) {
        cp16(&Ws[0][w_k    ][w_n], &W[(size_t)(kbeg + w_k    )*ND1 + n0 + w_n]);
        cp16(&Ws[0][w_k + 8][w_n], &W[(size_t)(kbeg + w_k + 8)*ND1 + n0 + w_n]);
    }
    cpcommit();

    const int NIT = KSEG / 16;   /* 375 */
    for (int it = 0; it < NIT; it++) {
        int nb = (it + 1) & 1;
        if (it + 1 < NIT) {
            int k0 = kbeg + (it + 1) * 16;
            cp16(&As[nb][a_k][a_m], &g_y[(k0 + a_k)*NB + a_m]);
            if (wok) {
                cp16(&Ws[nb][w_k    ][w_n], &W[(size_t)(k0 + w_k    )*ND1 + n0 + w_n]);
                cp16(&Ws[nb][w_k + 8][w_n], &W[(size_t)(k0 + w_k + 8)*ND1 + n0 + w_n]);
            }
        }
        cpcommit();
        cpwait1();
        __syncthreads();
        int bf = it & 1;
        #pragma unroll
        for (int kh = 0; kh < 2; kh++) {
            int kk = kh * 8;
            unsigned a[2][4], b[4][2];
            #pragma unroll
            for (int mf = 0; mf < 2; mf++) {
                int m = wm + mf*16 + g;
                a[mf][0] = tf32r(As[bf][kk + tg    ][m]);
                a[mf][1] = tf32r(As[bf][kk + tg    ][m + 8]);
                a[mf][2] = tf32r(As[bf][kk + tg + 4][m]);
                a[mf][3] = tf32r(As[bf][kk + tg + 4][m + 8]);
            }
            #pragma unroll
            for (int nf = 0; nf < 4; nf++) {
                int n = wn + nf*8 + g;
                b[nf][0] = tf32r(Ws[bf][kk + tg    ][n]);
                b[nf][1] = tf32r(Ws[bf][kk + tg + 4][n]);
            }
            #pragma unroll
            for (int mf = 0; mf < 2; mf++)
                #pragma unroll
                for (int nf = 0; nf < 4; nf++)
                    mma8(c[mf][nf], a[mf], b[nf]);
        }
        __syncthreads();
    }

    float* dst = g_part[blockIdx.y];
    #pragma unroll
    for (int mf = 0; mf < 2; mf++) {
        #pragma unroll
        for (int nf = 0; nf < 4; nf++) {
            int col = n0 + wn + nf*8 + tg*2;
            if (col < ND1) {
                int r0 = wm + mf*16 + g;
                *(float2*)&dst[r0*ND1 + col]       = make_float2(c[mf][nf][0], c[mf][nf][1]);
                *(float2*)&dst[(r0 + 8)*ND1 + col] = make_float2(c[mf][nf][2], c[mf][nf][3]);
            }
        }
    }
}

__global__ void __launch_bounds__(256) reduce1_kernel(const float* __restrict__ b1)
{
    int i = blockIdx.x * 256 + threadIdx.x;
    if (i >= NB*ND1) return;
    int n = i % ND1;
    float s = b1[n];
    #pragma unroll
    for (int p = 0; p < KSPLIT; p++) s += g_part[p][i];
    g_hidden[i] = fmaxf(s, 0.f);
}

/* ---------------- dense2 + sigmoid: block per batch, thread per out ------ */
__global__ void __launch_bounds__(320) dense2_kernel(const float* __restrict__ w2,
                                                     const float* __restrict__ b2,
                                                     float* __restrict__ out)
{
    __shared__ float hsh[ND1];
    int m = blockIdx.x, tid = threadIdx.x;
    for (int i = tid; i < ND1; i += 320) hsh[i] = g_hidden[m*ND1 + i];
    __syncthreads();
    if (tid >= ND2) return;
    float a0 = 0.f, a1 = 0.f, a2 = 0.f, a3 = 0.f;
    for (int k = 0; k < ND1; k += 4) {
        a0 = fmaf(hsh[k    ], w2[(k    )*ND2 + tid], a0);
        a1 = fmaf(hsh[k + 1], w2[(k + 1)*ND2 + tid], a1);
        a2 = fmaf(hsh[k + 2], w2[(k + 2)*ND2 + tid], a2);
        a3 = fmaf(hsh[k + 3], w2[(k + 3)*ND2 + tid], a3);
    }
    out[m*ND2 + tid] = sigf((a0 + a1) + (a2 + a3) + b2[tid]);
}

extern "C" void kernel_launch(void* const* d_in, const int* in_sizes, int n_in,
                              void* d_out, int out_size)
{
    const float* inputs = (const float*)d_in[0];
    const float* conv_w = (const float*)d_in[1];
    const float* conv_b = (const float*)d_in[2];
    const float* fw_k   = (const float*)d_in[3];
    const float* fw_rk  = (const float*)d_in[4];
    const float* fw_b   = (const float*)d_in[5];
    const float* bw_k   = (const float*)d_in[6];
    const float* bw_rk  = (const float*)d_in[7];
    const float* bw_b   = (const float*)d_in[8];
    const float* w1     = (const float*)d_in[9];
    const float* b1     = (const float*)d_in[10];
    const float* w2     = (const float*)d_in[11];
    const float* b2     = (const float*)d_in[12];
    float* out = (float*)d_out;

    cudaFuncSetAttribute(gru_kernel, cudaFuncAttributeMaxDynamicSharedMemorySize, GRU_SMEM);

    conv_kernel<<<dim3(FEAT/64, NB), 256>>>(inputs, conv_w, conv_b);
    xproj_mma<<<dim3(TPOOL, H3/64, 2), 256>>>(fw_k, bw_k, fw_b, bw_b);
    gru_kernel<<<GRU_BLOCKS, GRU_THREADS, GRU_SMEM>>>(fw_rk, bw_rk, fw_b, bw_b);
    dense1_mma<<<dim3(16, KSPLIT), 256>>>(w1);
    reduce1_kernel<<<(NB*ND1 + 255)/256, 256>>>(b1);
    dense2_kernel<<<NB, 320>>>(w2, b2, out);
}

// round 5
// speedup vs baseline: 1.4331x; 1.0357x over previous
#include <cuda_runtime.h>
#include <math.h>

#define NB 64
#define TIN 1000
#define CIN 4
#define FEAT 320
#define KW 26
#define POOLW 13
#define TPOOL 75
#define HU 320
#define H3 960
#define FLATN 48000
#define ND1 2000
#define ND2 301
#define KSPLIT 8
#define KSEG (FLATN / KSPLIT)

/* GRU v2: 16 CTAs per dir, 20 units each */
#define GB 16
#define JPC 20
#define GRU2_SMEM ((2*HU*64 + 64*66) * 4)

__device__ float g_pooled[NB*TPOOL*FEAT];
__device__ float g_xp[2][TPOOL*H3*NB];
__device__ float g_y[FLATN*NB];            /* tf32 bits, (flat, b) */
__device__ float g_htf[2][2][HU*NB];       /* tf32 bits, swizzled [k][m] */
__device__ float g_part[KSPLIT][NB*ND1];
__device__ float g_hidden[NB*ND1];
__device__ unsigned g_cnt2[2];
__device__ unsigned g_gen2[2];

__device__ __forceinline__ float sigf(float x) { return 1.0f / (1.0f + __expf(-x)); }

__device__ __forceinline__ void cp16(const void* dst, const void* src) {
    unsigned d = (unsigned)__cvta_generic_to_shared(dst);
    asm volatile("cp.async.cg.shared.global [%0], [%1], 16;\n" :: "r"(d), "l"(src));
}
__device__ __forceinline__ void cpcommit() { asm volatile("cp.async.commit_group;\n" ::); }
__device__ __forceinline__ void cpwait0()  { asm volatile("cp.async.wait_group 0;\n" ::); }
__device__ __forceinline__ void cpwait3()  { asm volatile("cp.async.wait_group 3;\n" ::); }
__device__ __forceinline__ unsigned tf32r(float x) {
    unsigned r; asm("cvt.rna.tf32.f32 %0, %1;\n" : "=r"(r) : "f"(x)); return r;
}
__device__ __forceinline__ void mma8(float* c, const unsigned* a, const unsigned* b) {
    asm volatile(
        "mma.sync.aligned.m16n8k8.row.col.f32.tf32.tf32.f32 "
        "{%0,%1,%2,%3},{%4,%5,%6,%7},{%8,%9},{%0,%1,%2,%3};\n"
        : "+f"(c[0]), "+f"(c[1]), "+f"(c[2]), "+f"(c[3])
        : "r"(a[0]), "r"(a[1]), "r"(a[2]), "r"(a[3]), "r"(b[0]), "r"(b[1]));
}
/* swizzled index for [k][64] tf32 operand tiles: conflict-free frag reads */
__device__ __forceinline__ int swz(int k, int m) { return k*64 + (m ^ ((k & 3) * 8)); }

/* ---------------- conv1d + relu + maxpool13 ------------------------------ */
__global__ void __launch_bounds__(256) conv_kernel(const float* __restrict__ in,
                                                   const float* __restrict__ cw,
                                                   const float* __restrict__ cb)
{
    __shared__ float xs[CIN*TIN];
    __shared__ float ws[KW*CIN*64];
    int b = blockIdx.y, f0 = blockIdx.x * 64, tid = threadIdx.x;

    for (int i = tid; i < CIN*TIN; i += 256)
        xs[(i & 3)*TIN + (i >> 2)] = in[b*TIN*CIN + i];
    for (int i = tid; i < KW*CIN*64; i += 256)
        ws[i] = cw[(i >> 6)*FEAT + f0 + (i & 63)];
    __syncthreads();

    int fl = tid & 31, tg = tid >> 5;
    float ba = cb[f0 + fl], bb = cb[f0 + 32 + fl];

    for (int tp = tg; tp < TPOOL; tp += 8) {
        int t0 = tp * POOLW;
        float aa[POOLW], ab[POOLW];
        #pragma unroll
        for (int p = 0; p < POOLW; p++) { aa[p] = ba; ab[p] = bb; }
        #pragma unroll 1
        for (int k = 0; k < KW; k++) {
            #pragma unroll
            for (int c = 0; c < CIN; c++) {
                float wa = ws[(k*CIN + c)*64 + fl];
                float wb = ws[(k*CIN + c)*64 + 32 + fl];
                const float* xp = &xs[c*TIN + t0 + k];
                #pragma unroll
                for (int p = 0; p < POOLW; p++) {
                    float xv = xp[p];
                    aa[p] = fmaf(xv, wa, aa[p]);
                    ab[p] = fmaf(xv, wb, ab[p]);
                }
            }
        }
        float ma = aa[0], mb = ab[0];
        #pragma unroll
        for (int p = 1; p < POOLW; p++) { ma = fmaxf(ma, aa[p]); mb = fmaxf(mb, ab[p]); }
        g_pooled[(b*TPOOL + tp)*FEAT + f0 + fl]      = fmaxf(ma, 0.f);
        g_pooled[(b*TPOOL + tp)*FEAT + f0 + 32 + fl] = fmaxf(mb, 0.f);
    }
}

/* ------- xproj via tf32 MMA ------- */
__global__ void __launch_bounds__(256) xproj_mma(const float* __restrict__ fwk,
                                                 const float* __restrict__ bwk,
                                                 const float* __restrict__ fwb,
                                                 const float* __restrict__ bwb)
{
    __shared__ __align__(16) float As[2][64][20];
    __shared__ __align__(16) float Ws[2][16][72];
    int m0 = blockIdx.x * 64, n0 = blockIdx.y * 64, dir = blockIdx.z;
    const float* Bk   = dir ? bwk : fwk;
    const float* bias = dir ? bwb : fwb;
    float* xp = g_xp[dir];

    int tid = threadIdx.x, warp = tid >> 5, lane = tid & 31;
    int g = lane >> 2, tg = lane & 3;
    int wm = (warp >> 2) * 32, wn = (warp & 3) * 16;
    int a_m = tid >> 2, a_k = (tid & 3) * 4;
    int w_k = tid >> 4, w_n = (tid & 15) * 4;

    float c[2][2][4] = {};

    cp16(&As[0][a_m][a_k], &g_pooled[(m0 + a_m)*FEAT + a_k]);
    cp16(&Ws[0][w_k][w_n], &Bk[w_k*H3 + n0 + w_n]);
    cpcommit();

    const int NIT = FEAT / 16;
    for (int it = 0; it < NIT; it++) {
        int nb = (it + 1) & 1;
        if (it + 1 < NIT) {
            int k0 = (it + 1) * 16;
            cp16(&As[nb][a_m][a_k], &g_pooled[(m0 + a_m)*FEAT + k0 + a_k]);
            cp16(&Ws[nb][w_k][w_n], &Bk[(k0 + w_k)*H3 + n0 + w_n]);
        }
        cpcommit();
        asm volatile("cp.async.wait_group 1;\n" ::);
        __syncthreads();
        int bf = it & 1;
        #pragma unroll
        for (int kh = 0; kh < 2; kh++) {
            int kk = kh * 8;
            unsigned a[2][4], b[2][2];
            #pragma unroll
            for (int mf = 0; mf < 2; mf++) {
                int m = wm + mf*16 + g;
                a[mf][0] = tf32r(As[bf][m    ][kk + tg]);
                a[mf][1] = tf32r(As[bf][m + 8][kk + tg]);
                a[mf][2] = tf32r(As[bf][m    ][kk + tg + 4]);
                a[mf][3] = tf32r(As[bf][m + 8][kk + tg + 4]);
            }
            #pragma unroll
            for (int nf = 0; nf < 2; nf++) {
                int n = wn + nf*8 + g;
                b[nf][0] = tf32r(Ws[bf][kk + tg    ][n]);
                b[nf][1] = tf32r(Ws[bf][kk + tg + 4][n]);
            }
            #pragma unroll
            for (int mf = 0; mf < 2; mf++)
                #pragma unroll
                for (int nf = 0; nf < 2; nf++)
                    mma8(c[mf][nf], a[mf], b[nf]);
        }
        __syncthreads();
    }

    #pragma unroll
    for (int mf = 0; mf < 2; mf++) {
        #pragma unroll
        for (int nf = 0; nf < 2; nf++) {
            int col = n0 + wn + nf*8 + tg*2;
            float bv0 = bias[col], bv1 = bias[col + 1];
            int r0 = m0 + wm + mf*16 + g;
            int b0 = r0 / TPOOL, t0 = r0 - b0*TPOOL;
            int r1 = r0 + 8;
            int b1 = r1 / TPOOL, t1 = r1 - b1*TPOOL;
            xp[(t0*H3 + col    )*NB + b0] = c[mf][nf][0] + bv0;
            xp[(t0*H3 + col + 1)*NB + b0] = c[mf][nf][1] + bv1;
            xp[(t1*H3 + col    )*NB + b1] = c[mf][nf][2] + bv0;
            xp[(t1*H3 + col + 1)*NB + b1] = c[mf][nf][3] + bv1;
        }
    }
}

/* ---------------- persistent GRU v2: tensor-core recurrence -------------- */
__global__ void __launch_bounds__(256, 1) gru2_kernel(
    const float* __restrict__ rk_fw, const float* __restrict__ rk_bw,
    const float* __restrict__ b_fw,  const float* __restrict__ b_bw)
{
    extern __shared__ float smg[];
    float* rks = smg;                 /* [320][64] tf32 bits, swizzled */
    float* hs  = smg + HU*64;         /* [320][64] tf32 bits, swizzled */
    float* pre = smg + 2*HU*64;       /* [64][66] fp32 */

    int bx = blockIdx.x, dir = bx >> 4, jb = bx & 15, j0 = jb * JPC;
    const float* rk = dir ? rk_bw : rk_fw;
    const float* br = (dir ? b_bw : b_fw) + H3;
    const float* xp = g_xp[dir];
    int tid = threadIdx.x;

    /* load + convert rk slice: col c<20 -> z(j0+c), 20..39 -> r, 40..59 -> h */
    for (int i = tid; i < HU*64; i += 256) {
        int k = i >> 6, c = i & 63;
        float v = 0.f;
        if (c < 60) {
            int gi = c / JPC, jj = c - gi*JPC;
            v = rk[k*H3 + gi*HU + j0 + jj];
        }
        rks[swz(k, c)] = __uint_as_float(tf32r(v));
    }
    __syncthreads();

    int warp = tid >> 5, lane = tid & 31;
    int g = lane >> 2, tg = lane & 3;
    int wm = (warp >> 1) * 16, wn = (warp & 1) * 32;

    int b = tid & 63, jq = tid >> 6;
    float hold[5] = {};
    float brz[5], brr[5], brh[5];
    #pragma unroll
    for (int i = 0; i < 5; i++) {
        int jg = j0 + i*4 + jq;
        brz[i] = br[jg]; brr[i] = br[HU + jg]; brh[i] = br[2*HU + jg];
    }

    float* buf0 = g_htf[dir][0];
    float* buf1 = g_htf[dir][1];
    const unsigned* hsu = (const unsigned*)hs;
    const unsigned* rku = (const unsigned*)rks;

    for (int s = 0; s < TPOOL; s++) {
        int tt = dir ? (TPOOL - 1 - s) : s;

        if (s > 0) {
            /* stage h (tf32 bits) written last step by all CTAs of this dir */
            const float4* src = (const float4*)((s & 1) ? buf0 : buf1);
            float4* hs4 = (float4*)hs;
            for (int i = tid; i < HU*64/4; i += 256)
                cp16(&hs4[i], &src[i]);
            cpcommit();
            cpwait0();
            __syncthreads();

            float c[4][4] = {};
            #pragma unroll 4
            for (int ks = 0; ks < 40; ks++) {
                int kk = ks * 8;
                unsigned a[4];
                a[0] = hsu[swz(kk + tg,     wm + g)];
                a[1] = hsu[swz(kk + tg,     wm + 8 + g)];
                a[2] = hsu[swz(kk + tg + 4, wm + g)];
                a[3] = hsu[swz(kk + tg + 4, wm + 8 + g)];
                #pragma unroll
                for (int nf = 0; nf < 4; nf++) {
                    unsigned bb[2];
                    bb[0] = rku[swz(kk + tg,     wn + nf*8 + g)];
                    bb[1] = rku[swz(kk + tg + 4, wn + nf*8 + g)];
                    mma8(c[nf], a, bb);
                }
            }
            #pragma unroll
            for (int nf = 0; nf < 4; nf++) {
                int n = wn + nf*8 + tg*2;
                pre[(n    )*66 + wm + g]     = c[nf][0];
                pre[(n + 1)*66 + wm + g]     = c[nf][1];
                pre[(n    )*66 + wm + 8 + g] = c[nf][2];
                pre[(n + 1)*66 + wm + 8 + g] = c[nf][3];
            }
            __syncthreads();
        }

        float* wb = (s & 1) ? buf1 : buf0;
        #pragma unroll
        for (int i = 0; i < 5; i++) {
            int jl = i*4 + jq, jg = j0 + jl;
            float mz = xp[(tt*H3 + jg)*NB + b];
            float mr = xp[(tt*H3 + HU + jg)*NB + b];
            float mh = xp[(tt*H3 + 2*HU + jg)*NB + b];
            float az = 0.f, ar = 0.f, ah = 0.f;
            if (s > 0) {
                az = pre[(jl       )*66 + b];
                ar = pre[(JPC + jl )*66 + b];
                ah = pre[(2*JPC + jl)*66 + b];
            }
            float z    = sigf(mz + az + brz[i]);
            float r    = sigf(mr + ar + brr[i]);
            float cand = tanhf(mh + r * (ah + brh[i]));
            float hn   = z * hold[i] + (1.f - z) * cand;
            hold[i] = hn;
            unsigned hb = tf32r(hn);
            g_y[((tt*2 + dir)*HU + jg)*NB + b] = __uint_as_float(hb);
            wb[swz(jg, b)] = __uint_as_float(hb);
        }

        if (s < TPOOL - 1) {
            __threadfence();
            __syncthreads();
            if (tid == 0) {
                unsigned gen = *((volatile unsigned*)&g_gen2[dir]);
                if (atomicAdd(&g_cnt2[dir], 1u) == GB - 1u) {
                    g_cnt2[dir] = 0u;
                    __threadfence();
                    atomicAdd(&g_gen2[dir], 1u);
                } else {
                    while (*((volatile unsigned*)&g_gen2[dir]) == gen) { }
                }
            }
            __syncthreads();
        }
    }
}

/* -------- dense1 via tf32 MMA, depth-4 cp.async pipeline ----------------- */
__global__ void __launch_bounds__(256) dense1_mma(const float* __restrict__ W)
{
    __shared__ __align__(16) float As[4][16][72];
    __shared__ __align__(16) float Ws[4][16][136];
    int n0 = blockIdx.x * 128;
    int kbeg = blockIdx.y * KSEG;
    int tid = threadIdx.x, warp = tid >> 5, lane = tid & 31;
    int g = lane >> 2, tg = lane & 3;
    int wm = (warp >> 2) * 32, wn = (warp & 3) * 32;

    int a_k = tid >> 4, a_m = (tid & 15) * 4;
    int w_k = tid >> 5, w_n = (tid & 31) * 4;
    bool wok = (n0 + w_n) < ND1;

    if (!wok) {
        #pragma unroll
        for (int bf = 0; bf < 4; bf++) {
            *(float4*)&Ws[bf][w_k    ][w_n] = make_float4(0,0,0,0);
            *(float4*)&Ws[bf][w_k + 8][w_n] = make_float4(0,0,0,0);
        }
    }

    float c[2][4][4] = {};

    const int NIT = KSEG / 16;   /* 375 */
    #pragma unroll
    for (int p = 0; p < 3; p++) {
        int k0 = kbeg + p*16;
        cp16(&As[p][a_k][a_m], &g_y[(k0 + a_k)*NB + a_m]);
        if (wok) {
            cp16(&Ws[p][w_k    ][w_n], &W[(size_t)(k0 + w_k    )*ND1 + n0 + w_n]);
            cp16(&Ws[p][w_k + 8][w_n], &W[(size_t)(k0 + w_k + 8)*ND1 + n0 + w_n]);
        }
        cpcommit();
    }

    for (int it = 0; it < NIT; it++) {
        if (it + 3 < NIT) {
            int p = (it + 3) & 3;
            int k0 = kbeg + (it + 3) * 16;
            cp16(&As[p][a_k][a_m], &g_y[(k0 + a_k)*NB + a_m]);
            if (wok) {
                cp16(&Ws[p][w_k    ][w_n], &W[(size_t)(k0 + w_k    )*ND1 + n0 + w_n]);
                cp16(&Ws[p][w_k + 8][w_n], &W[(size_t)(k0 + w_k + 8)*ND1 + n0 + w_n]);
            }
        }
        cpcommit();
        cpwait3();
        __syncthreads();
        int bf = it & 3;
        #pragma unroll
        for (int kh = 0; kh < 2; kh++) {
            int kk = kh * 8;
            unsigned a[2][4], b[4][2];
            #pragma unroll
            for (int mf = 0; mf < 2; mf++) {
                int m = wm + mf*16 + g;
                a[mf][0] = __float_as_uint(As[bf][kk + tg    ][m]);
                a[mf][1] = __float_as_uint(As[bf][kk + tg    ][m + 8]);
                a[mf][2] = __float_as_uint(As[bf][kk + tg + 4][m]);
                a[mf][3] = __float_as_uint(As[bf][kk + tg + 4][m + 8]);
            }
            #pragma unroll
            for (int nf = 0; nf < 4; nf++) {
                int n = wn + nf*8 + g;
                b[nf][0] = tf32r(Ws[bf][kk + tg    ][n]);
                b[nf][1] = tf32r(Ws[bf][kk + tg + 4][n]);
            }
            #pragma unroll
            for (int mf = 0; mf < 2; mf++)
                #pragma unroll
                for (int nf = 0; nf < 4; nf++)
                    mma8(c[mf][nf], a[mf], b[nf]);
        }
        __syncthreads();
    }

    float* dst = g_part[blockIdx.y];
    #pragma unroll
    for (int mf = 0; mf < 2; mf++) {
        #pragma unroll
        for (int nf = 0; nf < 4; nf++) {
            int col = n0 + wn + nf*8 + tg*2;
            if (col < ND1) {
                int r0 = wm + mf*16 + g;
                *(float2*)&dst[r0*ND1 + col]       = make_float2(c[mf][nf][0], c[mf][nf][1]);
                *(float2*)&dst[(r0 + 8)*ND1 + col] = make_float2(c[mf][nf][2], c[mf][nf][3]);
            }
        }
    }
}

__global__ void __launch_bounds__(256) reduce1_kernel(const float* __restrict__ b1)
{
    int i = blockIdx.x * 256 + threadIdx.x;
    if (i >= NB*ND1) return;
    int n = i % ND1;
    float s = b1[n];
    #pragma unroll
    for (int p = 0; p < KSPLIT; p++) s += g_part[p][i];
    g_hidden[i] = fmaxf(s, 0.f);
}

__global__ void __launch_bounds__(320) dense2_kernel(const float* __restrict__ w2,
                                                     const float* __restrict__ b2,
                                                     float* __restrict__ out)
{
    __shared__ float hsh[ND1];
    int m = blockIdx.x, tid = threadIdx.x;
    for (int i = tid; i < ND1; i += 320) hsh[i] = g_hidden[m*ND1 + i];
    __syncthreads();
    if (tid >= ND2) return;
    float a0 = 0.f, a1 = 0.f, a2 = 0.f, a3 = 0.f;
    for (int k = 0; k < ND1; k += 4) {
        a0 = fmaf(hsh[k    ], w2[(k    )*ND2 + tid], a0);
        a1 = fmaf(hsh[k + 1], w2[(k + 1)*ND2 + tid], a1);
        a2 = fmaf(hsh[k + 2], w2[(k + 2)*ND2 + tid], a2);
        a3 = fmaf(hsh[k + 3], w2[(k + 3)*ND2 + tid], a3);
    }
    out[m*ND2 + tid] = sigf((a0 + a1) + (a2 + a3) + b2[tid]);
}

extern "C" void kernel_launch(void* const* d_in, const int* in_sizes, int n_in,
                              void* d_out, int out_size)
{
    const float* inputs = (const float*)d_in[0];
    const float* conv_w = (const float*)d_in[1];
    const float* conv_b = (const float*)d_in[2];
    const float* fw_k   = (const float*)d_in[3];
    const float* fw_rk  = (const float*)d_in[4];
    const float* fw_b   = (const float*)d_in[5];
    const float* bw_k   = (const float*)d_in[6];
    const float* bw_rk  = (const float*)d_in[7];
    const float* bw_b   = (const float*)d_in[8];
    const float* w1     = (const float*)d_in[9];
    const float* b1     = (const float*)d_in[10];
    const float* w2     = (const float*)d_in[11];
    const float* b2     = (const float*)d_in[12];
    float* out = (float*)d_out;

    cudaFuncSetAttribute(gru2_kernel, cudaFuncAttributeMaxDynamicSharedMemorySize, GRU2_SMEM);

    conv_kernel<<<dim3(FEAT/64, NB), 256>>>(inputs, conv_w, conv_b);
    xproj_mma<<<dim3(TPOOL, H3/64, 2), 256>>>(fw_k, bw_k, fw_b, bw_b);
    gru2_kernel<<<2*GB, 256, GRU2_SMEM>>>(fw_rk, bw_rk, fw_b, bw_b);
    dense1_mma<<<dim3(16, KSPLIT), 256>>>(w1);
    reduce1_kernel<<<(NB*ND1 + 255)/256, 256>>>(b1);
    dense2_kernel<<<NB, 320>>>(w2, b2, out);
}

// round 6
// speedup vs baseline: 1.5540x; 1.0843x over previous
#include <cuda_runtime.h>
#include <math.h>

#define NB 64
#define TIN 1000
#define CIN 4
#define FEAT 320
#define KW 26
#define POOLW 13
#define TPOOL 75
#define HU 320
#define H3 960
#define FLATN 48000
#define ND1 2000
#define ND2 301
#define KSPLIT 20
#define KSEG (FLATN / KSPLIT)   /* 2400 */

/* GRU v3: 16 CTAs per dir, 20 units each, rk in registers */
#define GB 16
#define JPC 20
#define PRE_OFF (HU*64)
#define GRU3_SMEM ((HU*64 + 4*64*66) * 4)

__device__ float g_pooled[NB*TPOOL*FEAT];
__device__ float g_xp[2][TPOOL*H3*NB];
__device__ float g_y[FLATN*NB];            /* tf32 bits, (flat, b) */
__device__ float g_htf[2][2][HU*NB];       /* tf32 bits, swizzled [k][m] */
__device__ float g_part[KSPLIT][NB*ND1];
__device__ float g_hidden[NB*ND1];
__device__ unsigned g_cnt2[2];
__device__ unsigned g_gen2[2];

__device__ __forceinline__ float sigf(float x) { return 1.0f / (1.0f + __expf(-x)); }

__device__ __forceinline__ void cp16(const void* dst, const void* src) {
    unsigned d = (unsigned)__cvta_generic_to_shared(dst);
    asm volatile("cp.async.cg.shared.global [%0], [%1], 16;\n" :: "r"(d), "l"(src));
}
__device__ __forceinline__ void cpcommit() { asm volatile("cp.async.commit_group;\n" ::); }
__device__ __forceinline__ void cpwait0()  { asm volatile("cp.async.wait_group 0;\n" ::); }
__device__ __forceinline__ void cpwait3()  { asm volatile("cp.async.wait_group 3;\n" ::); }
__device__ __forceinline__ unsigned tf32r(float x) {
    unsigned r; asm("cvt.rna.tf32.f32 %0, %1;\n" : "=r"(r) : "f"(x)); return r;
}
__device__ __forceinline__ void mma8(float* c, const unsigned* a, const unsigned* b) {
    asm volatile(
        "mma.sync.aligned.m16n8k8.row.col.f32.tf32.tf32.f32 "
        "{%0,%1,%2,%3},{%4,%5,%6,%7},{%8,%9},{%0,%1,%2,%3};\n"
        : "+f"(c[0]), "+f"(c[1]), "+f"(c[2]), "+f"(c[3])
        : "r"(a[0]), "r"(a[1]), "r"(a[2]), "r"(a[3]), "r"(b[0]), "r"(b[1]));
}
__device__ __forceinline__ int swz(int k, int m) { return k*64 + (m ^ ((k & 3) * 8)); }

/* ---------------- conv1d + relu + maxpool13 ------------------------------ */
__global__ void __launch_bounds__(256) conv_kernel(const float* __restrict__ in,
                                                   const float* __restrict__ cw,
                                                   const float* __restrict__ cb)
{
    __shared__ float xs[CIN*TIN];
    __shared__ float ws[KW*CIN*64];
    int b = blockIdx.y, f0 = blockIdx.x * 64, tid = threadIdx.x;

    for (int i = tid; i < CIN*TIN; i += 256)
        xs[(i & 3)*TIN + (i >> 2)] = in[b*TIN*CIN + i];
    for (int i = tid; i < KW*CIN*64; i += 256)
        ws[i] = cw[(i >> 6)*FEAT + f0 + (i & 63)];
    __syncthreads();

    int fl = tid & 31, tg = tid >> 5;
    float ba = cb[f0 + fl], bb = cb[f0 + 32 + fl];

    for (int tp = tg; tp < TPOOL; tp += 8) {
        int t0 = tp * POOLW;
        float aa[POOLW], ab[POOLW];
        #pragma unroll
        for (int p = 0; p < POOLW; p++) { aa[p] = ba; ab[p] = bb; }
        #pragma unroll 1
        for (int k = 0; k < KW; k++) {
            #pragma unroll
            for (int c = 0; c < CIN; c++) {
                float wa = ws[(k*CIN + c)*64 + fl];
                float wb = ws[(k*CIN + c)*64 + 32 + fl];
                const float* xp = &xs[c*TIN + t0 + k];
                #pragma unroll
                for (int p = 0; p < POOLW; p++) {
                    float xv = xp[p];
                    aa[p] = fmaf(xv, wa, aa[p]);
                    ab[p] = fmaf(xv, wb, ab[p]);
                }
            }
        }
        float ma = aa[0], mb = ab[0];
        #pragma unroll
        for (int p = 1; p < POOLW; p++) { ma = fmaxf(ma, aa[p]); mb = fmaxf(mb, ab[p]); }
        g_pooled[(b*TPOOL + tp)*FEAT + f0 + fl]      = fmaxf(ma, 0.f);
        g_pooled[(b*TPOOL + tp)*FEAT + f0 + 32 + fl] = fmaxf(mb, 0.f);
    }
}

/* ------- xproj via tf32 MMA ------- */
__global__ void __launch_bounds__(256) xproj_mma(const float* __restrict__ fwk,
                                                 const float* __restrict__ bwk,
                                                 const float* __restrict__ fwb,
                                                 const float* __restrict__ bwb)
{
    __shared__ __align__(16) float As[2][64][20];
    __shared__ __align__(16) float Ws[2][16][72];
    int m0 = blockIdx.x * 64, n0 = blockIdx.y * 64, dir = blockIdx.z;
    const float* Bk   = dir ? bwk : fwk;
    const float* bias = dir ? bwb : fwb;
    float* xp = g_xp[dir];

    int tid = threadIdx.x, warp = tid >> 5, lane = tid & 31;
    int g = lane >> 2, tg = lane & 3;
    int wm = (warp >> 2) * 32, wn = (warp & 3) * 16;
    int a_m = tid >> 2, a_k = (tid & 3) * 4;
    int w_k = tid >> 4, w_n = (tid & 15) * 4;

    float c[2][2][4] = {};

    cp16(&As[0][a_m][a_k], &g_pooled[(m0 + a_m)*FEAT + a_k]);
    cp16(&Ws[0][w_k][w_n], &Bk[w_k*H3 + n0 + w_n]);
    cpcommit();

    const int NIT = FEAT / 16;
    for (int it = 0; it < NIT; it++) {
        int nb = (it + 1) & 1;
        if (it + 1 < NIT) {
            int k0 = (it + 1) * 16;
            cp16(&As[nb][a_m][a_k], &g_pooled[(m0 + a_m)*FEAT + k0 + a_k]);
            cp16(&Ws[nb][w_k][w_n], &Bk[(k0 + w_k)*H3 + n0 + w_n]);
        }
        cpcommit();
        asm volatile("cp.async.wait_group 1;\n" ::);
        __syncthreads();
        int bf = it & 1;
        #pragma unroll
        for (int kh = 0; kh < 2; kh++) {
            int kk = kh * 8;
            unsigned a[2][4], b[2][2];
            #pragma unroll
            for (int mf = 0; mf < 2; mf++) {
                int m = wm + mf*16 + g;
                a[mf][0] = tf32r(As[bf][m    ][kk + tg]);
                a[mf][1] = tf32r(As[bf][m + 8][kk + tg]);
                a[mf][2] = tf32r(As[bf][m    ][kk + tg + 4]);
                a[mf][3] = tf32r(As[bf][m + 8][kk + tg + 4]);
            }
            #pragma unroll
            for (int nf = 0; nf < 2; nf++) {
                int n = wn + nf*8 + g;
                b[nf][0] = tf32r(Ws[bf][kk + tg    ][n]);
                b[nf][1] = tf32r(Ws[bf][kk + tg + 4][n]);
            }
            #pragma unroll
            for (int mf = 0; mf < 2; mf++)
                #pragma unroll
                for (int nf = 0; nf < 2; nf++)
                    mma8(c[mf][nf], a[mf], b[nf]);
        }
        __syncthreads();
    }

    #pragma unroll
    for (int mf = 0; mf < 2; mf++) {
        #pragma unroll
        for (int nf = 0; nf < 2; nf++) {
            int col = n0 + wn + nf*8 + tg*2;
            float bv0 = bias[col], bv1 = bias[col + 1];
            int r0 = m0 + wm + mf*16 + g;
            int b0 = r0 / TPOOL, t0 = r0 - b0*TPOOL;
            int r1 = r0 + 8;
            int b1 = r1 / TPOOL, t1 = r1 - b1*TPOOL;
            xp[(t0*H3 + col    )*NB + b0] = c[mf][nf][0] + bv0;
            xp[(t0*H3 + col + 1)*NB + b0] = c[mf][nf][1] + bv1;
            xp[(t1*H3 + col    )*NB + b1] = c[mf][nf][2] + bv0;
            xp[(t1*H3 + col + 1)*NB + b1] = c[mf][nf][3] + bv1;
        }
    }
}

/* ------- persistent GRU v3: rk resident in registers, K-split warps ------ */
__global__ void __launch_bounds__(512, 1) gru3_kernel(
    const float* __restrict__ rk_fw, const float* __restrict__ rk_bw,
    const float* __restrict__ b_fw,  const float* __restrict__ b_bw)
{
    extern __shared__ float smg[];
    float* hs  = smg;                 /* [320][64] tf32 bits, swizzled; rk temp in prologue */
    float* pre = smg + PRE_OFF;       /* [4][64][66] fp32 partials */

    int bx = blockIdx.x, dir = bx >> 4, jb = bx & 15, j0 = jb * JPC;
    const float* rk = dir ? rk_bw : rk_fw;
    const float* br = (dir ? b_bw : b_fw) + H3;
    const float* xp = g_xp[dir];
    int tid = threadIdx.x, warp = tid >> 5, lane = tid & 31;
    int g = lane >> 2, tg = lane & 3;
    int nw  = (warp & 3) * 16;        /* n slice */
    int khq = warp >> 2;              /* k quarter 0..3 */
    int kh  = khq * 80;

    /* prologue: stage rk slice into hs (tf32, swizzled), extract B frags */
    for (int i = tid; i < HU*64; i += 512) {
        int k = i >> 6, c = i & 63;
        float v = 0.f;
        if (c < 60) {
            int gi = c / JPC, jj = c - gi*JPC;
            v = rk[k*H3 + gi*HU + j0 + jj];
        }
        hs[swz(k, c)] = __uint_as_float(tf32r(v));
    }
    __syncthreads();

    const unsigned* hsu = (const unsigned*)hs;
    unsigned Bf[10][2][2];
    #pragma unroll
    for (int ks = 0; ks < 10; ks++) {
        int kk = kh + ks*8;
        #pragma unroll
        for (int nf = 0; nf < 2; nf++) {
            int n = nw + nf*8 + g;
            Bf[ks][nf][0] = hsu[swz(kk + tg,     n)];
            Bf[ks][nf][1] = hsu[swz(kk + tg + 4, n)];
        }
    }
    __syncthreads();

    int b = tid & 63, jq = tid >> 6;  /* jq 0..7 */
    int nj = (jq < 4) ? 3 : 2;        /* units jl = jq + 8*i < 20 */
    float hold[3] = {0.f, 0.f, 0.f};
    float brz[3], brr[3], brh[3];
    #pragma unroll
    for (int i = 0; i < 3; i++) {
        int jl = jq + 8*i;
        int jg = j0 + ((jl < JPC) ? jl : 0);
        brz[i] = br[jg]; brr[i] = br[HU + jg]; brh[i] = br[2*HU + jg];
    }

    float* buf0 = g_htf[dir][0];
    float* buf1 = g_htf[dir][1];

    for (int s = 0; s < TPOOL; s++) {
        int tt = dir ? (TPOOL - 1 - s) : s;

        if (s > 0) {
            const float4* src = (const float4*)((s & 1) ? buf0 : buf1);
            float4* hs4 = (float4*)hs;
            for (int i = tid; i < HU*64/4; i += 512)
                cp16(&hs4[i], &src[i]);
            cpcommit();
            cpwait0();
            __syncthreads();

            float c[4][2][4] = {};
            #pragma unroll
            for (int ks = 0; ks < 10; ks++) {
                int kk = kh + ks*8;
                unsigned a[4][4];
                #pragma unroll
                for (int mt = 0; mt < 4; mt++) {
                    int m = mt*16;
                    a[mt][0] = hsu[swz(kk + tg,     m + g)];
                    a[mt][1] = hsu[swz(kk + tg,     m + 8 + g)];
                    a[mt][2] = hsu[swz(kk + tg + 4, m + g)];
                    a[mt][3] = hsu[swz(kk + tg + 4, m + 8 + g)];
                }
                #pragma unroll
                for (int mt = 0; mt < 4; mt++)
                    #pragma unroll
                    for (int nf = 0; nf < 2; nf++)
                        mma8(c[mt][nf], a[mt], Bf[ks][nf]);
            }
            float* pb = pre + khq*64*66;
            #pragma unroll
            for (int mt = 0; mt < 4; mt++) {
                #pragma unroll
                for (int nf = 0; nf < 2; nf++) {
                    int n = nw + nf*8 + tg*2;
                    int m = mt*16 + g;
                    pb[(n    )*66 + m]     = c[mt][nf][0];
                    pb[(n + 1)*66 + m]     = c[mt][nf][1];
                    pb[(n    )*66 + m + 8] = c[mt][nf][2];
                    pb[(n + 1)*66 + m + 8] = c[mt][nf][3];
                }
            }
            __syncthreads();
        }

        float* wb = (s & 1) ? buf1 : buf0;
        #pragma unroll
        for (int i = 0; i < 3; i++) {
            if (i >= nj) break;
            int jl = jq + 8*i, jg = j0 + jl;
            float mz = xp[(tt*H3 + jg)*NB + b];
            float mr = xp[(tt*H3 + HU + jg)*NB + b];
            float mh = xp[(tt*H3 + 2*HU + jg)*NB + b];
            float az = 0.f, ar = 0.f, ah = 0.f;
            if (s > 0) {
                #pragma unroll
                for (int p = 0; p < 4; p++) {
                    const float* pb = pre + p*64*66;
                    az += pb[(jl        )*66 + b];
                    ar += pb[(JPC + jl  )*66 + b];
                    ah += pb[(2*JPC + jl)*66 + b];
                }
            }
            float z    = sigf(mz + az + brz[i]);
            float r    = sigf(mr + ar + brr[i]);
            float cand = tanhf(mh + r * (ah + brh[i]));
            float hn   = z * hold[i] + (1.f - z) * cand;
            hold[i] = hn;
            unsigned hb = tf32r(hn);
            g_y[((tt*2 + dir)*HU + jg)*NB + b] = __uint_as_float(hb);
            wb[swz(jg, b)] = __uint_as_float(hb);
        }

        if (s < TPOOL - 1) {
            __threadfence();
            __syncthreads();
            if (tid == 0) {
                unsigned gen = *((volatile unsigned*)&g_gen2[dir]);
                if (atomicAdd(&g_cnt2[dir], 1u) == GB - 1u) {
                    g_cnt2[dir] = 0u;
                    __threadfence();
                    atomicAdd(&g_gen2[dir], 1u);
                } else {
                    while (*((volatile unsigned*)&g_gen2[dir]) == gen) { }
                }
            }
            __syncthreads();
        }
    }
}

/* -------- dense1 via tf32 MMA, depth-4 pipeline, KSPLIT=20 --------------- */
__global__ void __launch_bounds__(256) dense1_mma(const float* __restrict__ W)
{
    __shared__ __align__(16) float As[4][16][72];
    __shared__ __align__(16) float Ws[4][16][136];
    int n0 = blockIdx.x * 128;
    int kbeg = blockIdx.y * KSEG;
    int tid = threadIdx.x, warp = tid >> 5, lane = tid & 31;
    int g = lane >> 2, tg = lane & 3;
    int wm = (warp >> 2) * 32, wn = (warp & 3) * 32;

    int a_k = tid >> 4, a_m = (tid & 15) * 4;
    int w_k = tid >> 5, w_n = (tid & 31) * 4;
    bool wok = (n0 + w_n) < ND1;

    if (!wok) {
        #pragma unroll
        for (int bf = 0; bf < 4; bf++) {
            *(float4*)&Ws[bf][w_k    ][w_n] = make_float4(0,0,0,0);
            *(float4*)&Ws[bf][w_k + 8][w_n] = make_float4(0,0,0,0);
        }
    }

    float c[2][4][4] = {};

    const int NIT = KSEG / 16;   /* 150 */
    #pragma unroll
    for (int p = 0; p < 3; p++) {
        int k0 = kbeg + p*16;
        cp16(&As[p][a_k][a_m], &g_y[(k0 + a_k)*NB + a_m]);
        if (wok) {
            cp16(&Ws[p][w_k    ][w_n], &W[(size_t)(k0 + w_k    )*ND1 + n0 + w_n]);
            cp16(&Ws[p][w_k + 8][w_n], &W[(size_t)(k0 + w_k + 8)*ND1 + n0 + w_n]);
        }
        cpcommit();
    }

    for (int it = 0; it < NIT; it++) {
        if (it + 3 < NIT) {
            int p = (it + 3) & 3;
            int k0 = kbeg + (it + 3) * 16;
            cp16(&As[p][a_k][a_m], &g_y[(k0 + a_k)*NB + a_m]);
            if (wok) {
                cp16(&Ws[p][w_k    ][w_n], &W[(size_t)(k0 + w_k    )*ND1 + n0 + w_n]);
                cp16(&Ws[p][w_k + 8][w_n], &W[(size_t)(k0 + w_k + 8)*ND1 + n0 + w_n]);
            }
        }
        cpcommit();
        cpwait3();
        __syncthreads();
        int bf = it & 3;
        #pragma unroll
        for (int kh = 0; kh < 2; kh++) {
            int kk = kh * 8;
            unsigned a[2][4], b[4][2];
            #pragma unroll
            for (int mf = 0; mf < 2; mf++) {
                int m = wm + mf*16 + g;
                a[mf][0] = __float_as_uint(As[bf][kk + tg    ][m]);
                a[mf][1] = __float_as_uint(As[bf][kk + tg    ][m + 8]);
                a[mf][2] = __float_as_uint(As[bf][kk + tg + 4][m]);
                a[mf][3] = __float_as_uint(As[bf][kk + tg + 4][m + 8]);
            }
            #pragma unroll
            for (int nf = 0; nf < 4; nf++) {
                int n = wn + nf*8 + g;
                b[nf][0] = tf32r(Ws[bf][kk + tg    ][n]);
                b[nf][1] = tf32r(Ws[bf][kk + tg + 4][n]);
            }
            #pragma unroll
            for (int mf = 0; mf < 2; mf++)
                #pragma unroll
                for (int nf = 0; nf < 4; nf++)
                    mma8(c[mf][nf], a[mf], b[nf]);
        }
        __syncthreads();
    }

    float* dst = g_part[blockIdx.y];
    #pragma unroll
    for (int mf = 0; mf < 2; mf++) {
        #pragma unroll
        for (int nf = 0; nf < 4; nf++) {
            int col = n0 + wn + nf*8 + tg*2;
            if (col < ND1) {
                int r0 = wm + mf*16 + g;
                *(float2*)&dst[r0*ND1 + col]       = make_float2(c[mf][nf][0], c[mf][nf][1]);
                *(float2*)&dst[(r0 + 8)*ND1 + col] = make_float2(c[mf][nf][2], c[mf][nf][3]);
            }
        }
    }
}

__global__ void __launch_bounds__(256) reduce1_kernel(const float* __restrict__ b1)
{
    int i = blockIdx.x * 256 + threadIdx.x;
    if (i >= NB*ND1) return;
    int n = i % ND1;
    float s = b1[n];
    #pragma unroll
    for (int p = 0; p < KSPLIT; p++) s += g_part[p][i];
    g_hidden[i] = fmaxf(s, 0.f);
}

__global__ void __launch_bounds__(320) dense2_kernel(const float* __restrict__ w2,
                                                     const float* __restrict__ b2,
                                                     float* __restrict__ out)
{
    __shared__ float hsh[ND1];
    int m = blockIdx.x, tid = threadIdx.x;
    for (int i = tid; i < ND1; i += 320) hsh[i] = g_hidden[m*ND1 + i];
    __syncthreads();
    if (tid >= ND2) return;
    float a0 = 0.f, a1 = 0.f, a2 = 0.f, a3 = 0.f;
    for (int k = 0; k < ND1; k += 4) {
        a0 = fmaf(hsh[k    ], w2[(k    )*ND2 + tid], a0);
        a1 = fmaf(hsh[k + 1], w2[(k + 1)*ND2 + tid], a1);
        a2 = fmaf(hsh[k + 2], w2[(k + 2)*ND2 + tid], a2);
        a3 = fmaf(hsh[k + 3], w2[(k + 3)*ND2 + tid], a3);
    }
    out[m*ND2 + tid] = sigf((a0 + a1) + (a2 + a3) + b2[tid]);
}

extern "C" void kernel_launch(void* const* d_in, const int* in_sizes, int n_in,
                              void* d_out, int out_size)
{
    const float* inputs = (const float*)d_in[0];
    const float* conv_w = (const float*)d_in[1];
    const float* conv_b = (const float*)d_in[2];
    const float* fw_k   = (const float*)d_in[3];
    const float* fw_rk  = (const float*)d_in[4];
    const float* fw_b   = (const float*)d_in[5];
    const float* bw_k   = (const float*)d_in[6];
    const float* bw_rk  = (const float*)d_in[7];
    const float* bw_b   = (const float*)d_in[8];
    const float* w1     = (const float*)d_in[9];
    const float* b1     = (const float*)d_in[10];
    const float* w2     = (const float*)d_in[11];
    const float* b2     = (const float*)d_in[12];
    float* out = (float*)d_out;

    cudaFuncSetAttribute(gru3_kernel, cudaFuncAttributeMaxDynamicSharedMemorySize, GRU3_SMEM);

    conv_kernel<<<dim3(FEAT/64, NB), 256>>>(inputs, conv_w, conv_b);
    xproj_mma<<<dim3(TPOOL, H3/64, 2), 256>>>(fw_k, bw_k, fw_b, bw_b);
    gru3_kernel<<<2*GB, 512, GRU3_SMEM>>>(fw_rk, bw_rk, fw_b, bw_b);
    dense1_mma<<<dim3(16, KSPLIT), 256>>>(w1);
    reduce1_kernel<<<(NB*ND1 + 255)/256, 256>>>(b1);
    dense2_kernel<<<NB, 320>>>(w2, b2, out);
}

// round 7
// speedup vs baseline: 1.5605x; 1.0042x over previous
#include <cuda_runtime.h>
#include <math.h>

#define NB 64
#define TIN 1000
#define CIN 4
#define FEAT 320
#define KW 26
#define POOLW 13
#define TPOOL 75
#define HU 320
#define H3 960
#define FLATN 48000
#define ND1 2000
#define ND2 301
#define KSPLIT 25
#define KSEG (FLATN / KSPLIT)   /* 1920 */

#define GB 16
#define JPC 20
#define PRE_OFF (HU*64)
#define GRU3_SMEM ((HU*64 + 4*64*66) * 4)

__device__ float g_pooled[NB*TPOOL*FEAT];
__device__ float g_xp[2][TPOOL*H3*NB];
__device__ float g_y[FLATN*NB];            /* tf32 bits, (flat, b) */
__device__ float g_htf[2][2][HU*NB];       /* tf32 bits, swizzled [k][m] */
__device__ float g_part[KSPLIT][NB*ND1];
__device__ float g_hidden[NB*ND1];
__device__ unsigned g_cnt2[2];
__device__ unsigned g_gen2[2];

__device__ __forceinline__ float sigf(float x) { return 1.0f / (1.0f + __expf(-x)); }

__device__ __forceinline__ void cp16(const void* dst, const void* src) {
    unsigned d = (unsigned)__cvta_generic_to_shared(dst);
    asm volatile("cp.async.cg.shared.global [%0], [%1], 16;\n" :: "r"(d), "l"(src));
}
__device__ __forceinline__ void cpcommit() { asm volatile("cp.async.commit_group;\n" ::); }
__device__ __forceinline__ void cpwait0()  { asm volatile("cp.async.wait_group 0;\n" ::); }
__device__ __forceinline__ void cpwait3()  { asm volatile("cp.async.wait_group 3;\n" ::); }
__device__ __forceinline__ unsigned tf32r(float x) {
    unsigned r; asm("cvt.rna.tf32.f32 %0, %1;\n" : "=r"(r) : "f"(x)); return r;
}
__device__ __forceinline__ void mma8(float* c, const unsigned* a, const unsigned* b) {
    asm volatile(
        "mma.sync.aligned.m16n8k8.row.col.f32.tf32.tf32.f32 "
        "{%0,%1,%2,%3},{%4,%5,%6,%7},{%8,%9},{%0,%1,%2,%3};\n"
        : "+f"(c[0]), "+f"(c[1]), "+f"(c[2]), "+f"(c[3])
        : "r"(a[0]), "r"(a[1]), "r"(a[2]), "r"(a[3]), "r"(b[0]), "r"(b[1]));
}
__device__ __forceinline__ int swz(int k, int m) { return k*64 + (m ^ ((k & 3) * 8)); }

/* ---------------- conv1d + relu + maxpool13 (32-f blocks) ---------------- */
__global__ void __launch_bounds__(256) conv_kernel(const float* __restrict__ in,
                                                   const float* __restrict__ cw,
                                                   const float* __restrict__ cb)
{
    __shared__ float xs[CIN*TIN];
    __shared__ float ws[KW*CIN*32];
    int b = blockIdx.y, f0 = blockIdx.x * 32, tid = threadIdx.x;

    for (int i = tid; i < CIN*TIN; i += 256)
        xs[(i & 3)*TIN + (i >> 2)] = in[b*TIN*CIN + i];
    for (int i = tid; i < KW*CIN*32; i += 256)
        ws[i] = cw[(i >> 5)*FEAT + f0 + (i & 31)];
    __syncthreads();

    int fl = tid & 31, tg = tid >> 5;
    float ba = cb[f0 + fl];

    for (int tp = tg; tp < TPOOL; tp += 8) {
        int t0 = tp * POOLW;
        float aa[POOLW];
        #pragma unroll
        for (int p = 0; p < POOLW; p++) aa[p] = ba;
        #pragma unroll 1
        for (int k = 0; k < KW; k++) {
            #pragma unroll
            for (int c = 0; c < CIN; c++) {
                float wa = ws[(k*CIN + c)*32 + fl];
                const float* xp = &xs[c*TIN + t0 + k];
                #pragma unroll
                for (int p = 0; p < POOLW; p++)
                    aa[p] = fmaf(xp[p], wa, aa[p]);
            }
        }
        float ma = aa[0];
        #pragma unroll
        for (int p = 1; p < POOLW; p++) ma = fmaxf(ma, aa[p]);
        g_pooled[(b*TPOOL + tp)*FEAT + f0 + fl] = fmaxf(ma, 0.f);
    }
}

/* ------- xproj via tf32 MMA ------- */
__global__ void __launch_bounds__(256) xproj_mma(const float* __restrict__ fwk,
                                                 const float* __restrict__ bwk,
                                                 const float* __restrict__ fwb,
                                                 const float* __restrict__ bwb)
{
    __shared__ __align__(16) float As[2][64][20];
    __shared__ __align__(16) float Ws[2][16][72];
    int m0 = blockIdx.x * 64, n0 = blockIdx.y * 64, dir = blockIdx.z;
    const float* Bk   = dir ? bwk : fwk;
    const float* bias = dir ? bwb : fwb;
    float* xp = g_xp[dir];

    int tid = threadIdx.x, warp = tid >> 5, lane = tid & 31;
    int g = lane >> 2, tg = lane & 3;
    int wm = (warp >> 2) * 32, wn = (warp & 3) * 16;
    int a_m = tid >> 2, a_k = (tid & 3) * 4;
    int w_k = tid >> 4, w_n = (tid & 15) * 4;

    float c[2][2][4] = {};

    cp16(&As[0][a_m][a_k], &g_pooled[(m0 + a_m)*FEAT + a_k]);
    cp16(&Ws[0][w_k][w_n], &Bk[w_k*H3 + n0 + w_n]);
    cpcommit();

    const int NIT = FEAT / 16;
    for (int it = 0; it < NIT; it++) {
        int nb = (it + 1) & 1;
        if (it + 1 < NIT) {
            int k0 = (it + 1) * 16;
            cp16(&As[nb][a_m][a_k], &g_pooled[(m0 + a_m)*FEAT + k0 + a_k]);
            cp16(&Ws[nb][w_k][w_n], &Bk[(k0 + w_k)*H3 + n0 + w_n]);
        }
        cpcommit();
        asm volatile("cp.async.wait_group 1;\n" ::);
        __syncthreads();
        int bf = it & 1;
        #pragma unroll
        for (int kh = 0; kh < 2; kh++) {
            int kk = kh * 8;
            unsigned a[2][4], b[2][2];
            #pragma unroll
            for (int mf = 0; mf < 2; mf++) {
                int m = wm + mf*16 + g;
                a[mf][0] = tf32r(As[bf][m    ][kk + tg]);
                a[mf][1] = tf32r(As[bf][m + 8][kk + tg]);
                a[mf][2] = tf32r(As[bf][m    ][kk + tg + 4]);
                a[mf][3] = tf32r(As[bf][m + 8][kk + tg + 4]);
            }
            #pragma unroll
            for (int nf = 0; nf < 2; nf++) {
                int n = wn + nf*8 + g;
                b[nf][0] = tf32r(Ws[bf][kk + tg    ][n]);
                b[nf][1] = tf32r(Ws[bf][kk + tg + 4][n]);
            }
            #pragma unroll
            for (int mf = 0; mf < 2; mf++)
                #pragma unroll
                for (int nf = 0; nf < 2; nf++)
                    mma8(c[mf][nf], a[mf], b[nf]);
        }
        __syncthreads();
    }

    #pragma unroll
    for (int mf = 0; mf < 2; mf++) {
        #pragma unroll
        for (int nf = 0; nf < 2; nf++) {
            int col = n0 + wn + nf*8 + tg*2;
            float bv0 = bias[col], bv1 = bias[col + 1];
            int r0 = m0 + wm + mf*16 + g;
            int b0 = r0 / TPOOL, t0 = r0 - b0*TPOOL;
            int r1 = r0 + 8;
            int b1 = r1 / TPOOL, t1 = r1 - b1*TPOOL;
            xp[(t0*H3 + col    )*NB + b0] = c[mf][nf][0] + bv0;
            xp[(t0*H3 + col + 1)*NB + b0] = c[mf][nf][1] + bv1;
            xp[(t1*H3 + col    )*NB + b1] = c[mf][nf][2] + bv0;
            xp[(t1*H3 + col + 1)*NB + b1] = c[mf][nf][3] + bv1;
        }
    }
}

/* ------- persistent GRU v3.1: split arrive/wait barrier + mx prefetch ---- */
__global__ void __launch_bounds__(512, 1) gru3_kernel(
    const float* __restrict__ rk_fw, const float* __restrict__ rk_bw,
    const float* __restrict__ b_fw,  const float* __restrict__ b_bw)
{
    extern __shared__ float smg[];
    float* hs  = smg;                 /* [320][64] tf32 bits, swizzled */
    float* pre = smg + PRE_OFF;       /* [4][64][66] fp32 partials */

    int bx = blockIdx.x, dir = bx >> 4, jb = bx & 15, j0 = jb * JPC;
    const float* rk = dir ? rk_bw : rk_fw;
    const float* br = (dir ? b_bw : b_fw) + H3;
    const float* xp = g_xp[dir];
    int tid = threadIdx.x, warp = tid >> 5, lane = tid & 31;
    int g = lane >> 2, tg = lane & 3;
    int nw  = (warp & 3) * 16;
    int khq = warp >> 2;
    int kh  = khq * 80;

    for (int i = tid; i < HU*64; i += 512) {
        int k = i >> 6, c = i & 63;
        float v = 0.f;
        if (c < 60) {
            int gi = c / JPC, jj = c - gi*JPC;
            v = rk[k*H3 + gi*HU + j0 + jj];
        }
        hs[swz(k, c)] = __uint_as_float(tf32r(v));
    }
    __syncthreads();

    const unsigned* hsu = (const unsigned*)hs;
    unsigned Bf[10][2][2];
    #pragma unroll
    for (int ks = 0; ks < 10; ks++) {
        int kk = kh + ks*8;
        #pragma unroll
        for (int nf = 0; nf < 2; nf++) {
            int n = nw + nf*8 + g;
            Bf[ks][nf][0] = hsu[swz(kk + tg,     n)];
            Bf[ks][nf][1] = hsu[swz(kk + tg + 4, n)];
        }
    }
    __syncthreads();

    int b = tid & 63, jq = tid >> 6;
    int nj = (jq < 4) ? 3 : 2;
    float hold[3] = {0.f, 0.f, 0.f};
    float brz[3], brr[3], brh[3];
    #pragma unroll
    for (int i = 0; i < 3; i++) {
        int jl = jq + 8*i;
        int jg = j0 + ((jl < JPC) ? jl : 0);
        brz[i] = br[jg]; brr[i] = br[HU + jg]; brh[i] = br[2*HU + jg];
    }

    float* buf0 = g_htf[dir][0];
    float* buf1 = g_htf[dir][1];

    /* prefetch mx for step 0 */
    float mzp[3], mrp[3], mhp[3];
    {
        int tt0 = dir ? (TPOOL - 1) : 0;
        #pragma unroll
        for (int i = 0; i < 3; i++) {
            int jl = jq + 8*i, jg = j0 + ((jl < JPC) ? jl : 0);
            mzp[i] = xp[(tt0*H3 + jg)*NB + b];
            mrp[i] = xp[(tt0*H3 + HU + jg)*NB + b];
            mhp[i] = xp[(tt0*H3 + 2*HU + jg)*NB + b];
        }
    }
    unsigned mygen = 0;

    for (int s = 0; s < TPOOL; s++) {
        int tt = dir ? (TPOOL - 1 - s) : s;

        if (s > 0) {
            /* ---- wait phase of split barrier ---- */
            if (tid == 0) {
                while (*((volatile unsigned*)&g_gen2[dir]) == mygen) { }
            }
            __syncthreads();

            const float4* src = (const float4*)((s & 1) ? buf0 : buf1);
            float4* hs4 = (float4*)hs;
            for (int i = tid; i < HU*64/4; i += 512)
                cp16(&hs4[i], &src[i]);
            cpcommit();
            cpwait0();
            __syncthreads();

            float c[4][2][4] = {};
            #pragma unroll
            for (int ks = 0; ks < 10; ks++) {
                int kk = kh + ks*8;
                unsigned a[4][4];
                #pragma unroll
                for (int mt = 0; mt < 4; mt++) {
                    int m = mt*16;
                    a[mt][0] = hsu[swz(kk + tg,     m + g)];
                    a[mt][1] = hsu[swz(kk + tg,     m + 8 + g)];
                    a[mt][2] = hsu[swz(kk + tg + 4, m + g)];
                    a[mt][3] = hsu[swz(kk + tg + 4, m + 8 + g)];
                }
                #pragma unroll
                for (int mt = 0; mt < 4; mt++)
                    #pragma unroll
                    for (int nf = 0; nf < 2; nf++)
                        mma8(c[mt][nf], a[mt], Bf[ks][nf]);
            }
            float* pb = pre + khq*64*66;
            #pragma unroll
            for (int mt = 0; mt < 4; mt++) {
                #pragma unroll
                for (int nf = 0; nf < 2; nf++) {
                    int n = nw + nf*8 + tg*2;
                    int m = mt*16 + g;
                    pb[(n    )*66 + m]     = c[mt][nf][0];
                    pb[(n + 1)*66 + m]     = c[mt][nf][1];
                    pb[(n    )*66 + m + 8] = c[mt][nf][2];
                    pb[(n + 1)*66 + m + 8] = c[mt][nf][3];
                }
            }
            __syncthreads();
        }

        float* wb = (s & 1) ? buf1 : buf0;
        #pragma unroll
        for (int i = 0; i < 3; i++) {
            if (i >= nj) break;
            int jl = jq + 8*i, jg = j0 + jl;
            float az = 0.f, ar = 0.f, ah = 0.f;
            if (s > 0) {
                #pragma unroll
                for (int p = 0; p < 4; p++) {
                    const float* pb = pre + p*64*66;
                    az += pb[(jl        )*66 + b];
                    ar += pb[(JPC + jl  )*66 + b];
                    ah += pb[(2*JPC + jl)*66 + b];
                }
            }
            float z    = sigf(mzp[i] + az + brz[i]);
            float r    = sigf(mrp[i] + ar + brr[i]);
            float cand = tanhf(mhp[i] + r * (ah + brh[i]));
            float hn   = z * hold[i] + (1.f - z) * cand;
            hold[i] = hn;
            unsigned hb = tf32r(hn);
            g_y[((tt*2 + dir)*HU + jg)*NB + b] = __uint_as_float(hb);
            wb[swz(jg, b)] = __uint_as_float(hb);
        }

        if (s < TPOOL - 1) {
            /* ---- arrive phase of split barrier ---- */
            __threadfence();
            __syncthreads();
            if (tid == 0) {
                mygen = *((volatile unsigned*)&g_gen2[dir]);
                if (atomicAdd(&g_cnt2[dir], 1u) == GB - 1u) {
                    g_cnt2[dir] = 0u;
                    __threadfence();
                    atomicAdd(&g_gen2[dir], 1u);
                }
            }
            /* overlap: prefetch mx for step s+1 while waiting */
            int tn = dir ? (TPOOL - 2 - s) : (s + 1);
            #pragma unroll
            for (int i = 0; i < 3; i++) {
                int jl = jq + 8*i, jg = j0 + ((jl < JPC) ? jl : 0);
                mzp[i] = xp[(tn*H3 + jg)*NB + b];
                mrp[i] = xp[(tn*H3 + HU + jg)*NB + b];
                mhp[i] = xp[(tn*H3 + 2*HU + jg)*NB + b];
            }
        }
    }
}

/* -------- dense1 via tf32 MMA, depth-4 pipeline, KSPLIT=25 --------------- */
__global__ void __launch_bounds__(256) dense1_mma(const float* __restrict__ W)
{
    __shared__ __align__(16) float As[4][16][72];
    __shared__ __align__(16) float Ws[4][16][136];
    int n0 = blockIdx.x * 128;
    int kbeg = blockIdx.y * KSEG;
    int tid = threadIdx.x, warp = tid >> 5, lane = tid & 31;
    int g = lane >> 2, tg = lane & 3;
    int wm = (warp >> 2) * 32, wn = (warp & 3) * 32;

    int a_k = tid >> 4, a_m = (tid & 15) * 4;
    int w_k = tid >> 5, w_n = (tid & 31) * 4;
    bool wok = (n0 + w_n) < ND1;

    if (!wok) {
        #pragma unroll
        for (int bf = 0; bf < 4; bf++) {
            *(float4*)&Ws[bf][w_k    ][w_n] = make_float4(0,0,0,0);
            *(float4*)&Ws[bf][w_k + 8][w_n] = make_float4(0,0,0,0);
        }
    }

    float c[2][4][4] = {};

    const int NIT = KSEG / 16;   /* 120 */
    #pragma unroll
    for (int p = 0; p < 3; p++) {
        int k0 = kbeg + p*16;
        cp16(&As[p][a_k][a_m], &g_y[(k0 + a_k)*NB + a_m]);
        if (wok) {
            cp16(&Ws[p][w_k    ][w_n], &W[(size_t)(k0 + w_k    )*ND1 + n0 + w_n]);
            cp16(&Ws[p][w_k + 8][w_n], &W[(size_t)(k0 + w_k + 8)*ND1 + n0 + w_n]);
        }
        cpcommit();
    }

    for (int it = 0; it < NIT; it++) {
        if (it + 3 < NIT) {
            int p = (it + 3) & 3;
            int k0 = kbeg + (it + 3) * 16;
            cp16(&As[p][a_k][a_m], &g_y[(k0 + a_k)*NB + a_m]);
            if (wok) {
                cp16(&Ws[p][w_k    ][w_n], &W[(size_t)(k0 + w_k    )*ND1 + n0 + w_n]);
                cp16(&Ws[p][w_k + 8][w_n], &W[(size_t)(k0 + w_k + 8)*ND1 + n0 + w_n]);
            }
        }
        cpcommit();
        cpwait3();
        __syncthreads();
        int bf = it & 3;
        #pragma unroll
        for (int kh = 0; kh < 2; kh++) {
            int kk = kh * 8;
            unsigned a[2][4], b[4][2];
            #pragma unroll
            for (int mf = 0; mf < 2; mf++) {
                int m = wm + mf*16 + g;
                a[mf][0] = __float_as_uint(As[bf][kk + tg    ][m]);
                a[mf][1] = __float_as_uint(As[bf][kk + tg    ][m + 8]);
                a[mf][2] = __float_as_uint(As[bf][kk + tg + 4][m]);
                a[mf][3] = __float_as_uint(As[bf][kk + tg + 4][m + 8]);
            }
            #pragma unroll
            for (int nf = 0; nf < 4; nf++) {
                int n = wn + nf*8 + g;
                b[nf][0] = tf32r(Ws[bf][kk + tg    ][n]);
                b[nf][1] = tf32r(Ws[bf][kk + tg + 4][n]);
            }
            #pragma unroll
            for (int mf = 0; mf < 2; mf++)
                #pragma unroll
                for (int nf = 0; nf < 4; nf++)
                    mma8(c[mf][nf], a[mf], b[nf]);
        }
        __syncthreads();
    }

    float* dst = g_part[blockIdx.y];
    #pragma unroll
    for (int mf = 0; mf < 2; mf++) {
        #pragma unroll
        for (int nf = 0; nf < 4; nf++) {
            int col = n0 + wn + nf*8 + tg*2;
            if (col < ND1) {
                int r0 = wm + mf*16 + g;
                *(float2*)&dst[r0*ND1 + col]       = make_float2(c[mf][nf][0], c[mf][nf][1]);
                *(float2*)&dst[(r0 + 8)*ND1 + col] = make_float2(c[mf][nf][2], c[mf][nf][3]);
            }
        }
    }
}

__global__ void __launch_bounds__(256) reduce1_kernel(const float* __restrict__ b1)
{
    int i = blockIdx.x * 256 + threadIdx.x;
    if (i >= NB*ND1) return;
    int n = i % ND1;
    float s = b1[n];
    #pragma unroll
    for (int p = 0; p < KSPLIT; p++) s += g_part[p][i];
    g_hidden[i] = fmaxf(s, 0.f);
}

/* ---------------- dense2: 2 batches per block ---------------------------- */
__global__ void __launch_bounds__(320) dense2_kernel(const float* __restrict__ w2,
                                                     const float* __restrict__ b2,
                                                     float* __restrict__ out)
{
    __shared__ float hsh[2*ND1];
    int m0 = blockIdx.x * 2, tid = threadIdx.x;
    for (int i = tid; i < 2*ND1; i += 320) hsh[i] = g_hidden[m0*ND1 + i];
    __syncthreads();
    if (tid >= ND2) return;
    float a0 = 0.f, a1 = 0.f, c0 = 0.f, c1 = 0.f;
    for (int k = 0; k < ND1; k += 2) {
        float w0 = w2[(k    )*ND2 + tid];
        float w1 = w2[(k + 1)*ND2 + tid];
        a0 = fmaf(hsh[k], w0, a0);       a1 = fmaf(hsh[k + 1], w1, a1);
        c0 = fmaf(hsh[ND1 + k], w0, c0); c1 = fmaf(hsh[ND1 + k + 1], w1, c1);
    }
    float bb = b2[tid];
    out[m0*ND2 + tid]       = sigf(a0 + a1 + bb);
    out[(m0 + 1)*ND2 + tid] = sigf(c0 + c1 + bb);
}

extern "C" void kernel_launch(void* const* d_in, const int* in_sizes, int n_in,
                              void* d_out, int out_size)
{
    const float* inputs = (const float*)d_in[0];
    const float* conv_w = (const float*)d_in[1];
    const float* conv_b = (const float*)d_in[2];
    const float* fw_k   = (const float*)d_in[3];
    const float* fw_rk  = (const float*)d_in[4];
    const float* fw_b   = (const float*)d_in[5];
    const float* bw_k   = (const float*)d_in[6];
    const float* bw_rk  = (const float*)d_in[7];
    const float* bw_b   = (const float*)d_in[8];
    const float* w1     = (const float*)d_in[9];
    const float* b1     = (const float*)d_in[10];
    const float* w2     = (const float*)d_in[11];
    const float* b2     = (const float*)d_in[12];
    float* out = (float*)d_out;

    cudaFuncSetAttribute(gru3_kernel, cudaFuncAttributeMaxDynamicSharedMemorySize, GRU3_SMEM);

    conv_kernel<<<dim3(FEAT/32, NB), 256>>>(inputs, conv_w, conv_b);
    xproj_mma<<<dim3(TPOOL, H3/64, 2), 256>>>(fw_k, bw_k, fw_b, bw_b);
    gru3_kernel<<<2*GB, 512, GRU3_SMEM>>>(fw_rk, bw_rk, fw_b, bw_b);
    dense1_mma<<<dim3(16, KSPLIT), 256>>>(w1);
    reduce1_kernel<<<(NB*ND1 + 255)/256, 256>>>(b1);
    dense2_kernel<<<NB/2, 320>>>(w2, b2, out);
}

// round 8
// speedup vs baseline: 1.9948x; 1.2783x over previous
#include <cuda_runtime.h>
#include <math.h>

#define NB 64
#define TIN 1000
#define CIN 4
#define FEAT 320
#define KW 26
#define POOLW 13
#define TPOOL 75
#define HU 320
#define H3 960
#define FLATN 48000
#define ND1 2000
#define ND2 301
#define KSPLIT 40
#define KSEG (FLATN / KSPLIT)   /* 1200 */

#define GB 16
#define JPC 20
#define PRE_OFF (HU*64)
#define GRU4_SMEM ((HU*64 + 2*64*66) * 4)

#define XSTR 1032   /* xs row stride (floats): 1032%32=8 -> conflict-free A frags */

__device__ float g_pooled[NB*TPOOL*FEAT];
__device__ float g_xp[2][TPOOL*H3*NB];
__device__ float g_y[FLATN*NB];            /* tf32 bits, (flat, b) */
__device__ float g_htf[2][2][HU*NB];       /* tf32 bits, swizzled [k][m] */
__device__ float g_part[KSPLIT][NB*ND1];
__device__ float g_hidden[NB*ND1];
__device__ unsigned g_cnt2[2];
__device__ unsigned g_gen2[2];

__device__ __forceinline__ float sigf(float x) { return 1.0f / (1.0f + __expf(-x)); }

__device__ __forceinline__ void cp16(const void* dst, const void* src) {
    unsigned d = (unsigned)__cvta_generic_to_shared(dst);
    asm volatile("cp.async.cg.shared.global [%0], [%1], 16;\n" :: "r"(d), "l"(src));
}
__device__ __forceinline__ void cpcommit() { asm volatile("cp.async.commit_group;\n" ::); }
__device__ __forceinline__ void cpwait0()  { asm volatile("cp.async.wait_group 0;\n" ::); }
__device__ __forceinline__ void cpwait3()  { asm volatile("cp.async.wait_group 3;\n" ::); }
__device__ __forceinline__ unsigned tf32r(float x) {
    unsigned r; asm("cvt.rna.tf32.f32 %0, %1;\n" : "=r"(r) : "f"(x)); return r;
}
__device__ __forceinline__ void mma8(float* c, const unsigned* a, const unsigned* b) {
    asm volatile(
        "mma.sync.aligned.m16n8k8.row.col.f32.tf32.tf32.f32 "
        "{%0,%1,%2,%3},{%4,%5,%6,%7},{%8,%9},{%0,%1,%2,%3};\n"
        : "+f"(c[0]), "+f"(c[1]), "+f"(c[2]), "+f"(c[3])
        : "r"(a[0]), "r"(a[1]), "r"(a[2]), "r"(a[3]), "r"(b[0]), "r"(b[1]));
}
__device__ __forceinline__ int swz(int k, int m) { return k*64 + (m ^ ((k & 3) * 8)); }

/* -------- conv1d + relu + maxpool13 via tf32 MMA (implicit im2col) ------- */
/* grid (5, 64): CTA = (64 features, one batch). A[t][kc]=x[kc&3][t+(kc>>2)] */
__global__ void __launch_bounds__(256) conv_mma(const float* __restrict__ in,
                                                const float* __restrict__ cw,
                                                const float* __restrict__ cb)
{
    __shared__ __align__(16) float xs[CIN*XSTR];
    __shared__ __align__(16) float Ws[KW*CIN*72];
    int b = blockIdx.y, n0 = blockIdx.x * 64, tid = threadIdx.x;

    /* Ws[kc][n] for n in [n0, n0+64) */
    for (int i = tid; i < 104*16; i += 256) {
        int kc = i >> 4, nq = (i & 15) * 4;
        cp16(&Ws[kc*72 + nq], &cw[kc*FEAT + n0 + nq]);
    }
    /* xs transposed [c][t] */
    for (int i = tid; i < TIN*CIN; i += 256)
        xs[(i & 3)*XSTR + (i >> 2)] = in[b*TIN*CIN + i];
    if (tid < 4*32) {
        int c = tid >> 5, t = TIN + (tid & 31);
        if (t < XSTR) xs[c*XSTR + t] = 0.f;
    }
    cpcommit(); cpwait0();
    __syncthreads();

    int warp = tid >> 5, lane = tid & 31, g = lane >> 2, tg = lane & 3;
    bool row2ok = (g + 8) < POOLW;

    for (int tp = warp; tp < TPOOL; tp += 8) {
        int t0 = tp * POOLW;
        float c[8][4] = {};
        const float* xrow = &xs[tg*XSTR + t0 + g];
        #pragma unroll
        for (int ks = 0; ks < 13; ks++) {
            unsigned a[4];
            a[0] = tf32r(xrow[2*ks]);
            a[1] = tf32r(xrow[8 + 2*ks]);
            a[2] = tf32r(xrow[2*ks + 1]);
            a[3] = tf32r(xrow[8 + 2*ks + 1]);
            int kk = ks * 8;
            #pragma unroll
            for (int nf = 0; nf < 8; nf++) {
                unsigned bb[2];
                bb[0] = tf32r(Ws[(kk + tg    )*72 + nf*8 + g]);
                bb[1] = tf32r(Ws[(kk + tg + 4)*72 + nf*8 + g]);
                mma8(c[nf], a, bb);
            }
        }
        #pragma unroll
        for (int nf = 0; nf < 8; nf++) {
            float m0 = row2ok ? fmaxf(c[nf][0], c[nf][2]) : c[nf][0];
            float m1 = row2ok ? fmaxf(c[nf][1], c[nf][3]) : c[nf][1];
            #pragma unroll
            for (int off = 4; off < 32; off <<= 1) {
                m0 = fmaxf(m0, __shfl_xor_sync(0xffffffffu, m0, off));
                m1 = fmaxf(m1, __shfl_xor_sync(0xffffffffu, m1, off));
            }
            if (g == 0) {
                int col = n0 + nf*8 + tg*2;
                g_pooled[(b*TPOOL + tp)*FEAT + col]     = fmaxf(m0 + cb[col], 0.f);
                g_pooled[(b*TPOOL + tp)*FEAT + col + 1] = fmaxf(m1 + cb[col + 1], 0.f);
            }
        }
    }
}

/* ------- xproj via tf32 MMA ------- */
__global__ void __launch_bounds__(256) xproj_mma(const float* __restrict__ fwk,
                                                 const float* __restrict__ bwk,
                                                 const float* __restrict__ fwb,
                                                 const float* __restrict__ bwb)
{
    __shared__ __align__(16) float As[2][64][20];
    __shared__ __align__(16) float Ws[2][16][72];
    int m0 = blockIdx.x * 64, n0 = blockIdx.y * 64, dir = blockIdx.z;
    const float* Bk   = dir ? bwk : fwk;
    const float* bias = dir ? bwb : fwb;
    float* xp = g_xp[dir];

    int tid = threadIdx.x, warp = tid >> 5, lane = tid & 31;
    int g = lane >> 2, tg = lane & 3;
    int wm = (warp >> 2) * 32, wn = (warp & 3) * 16;
    int a_m = tid >> 2, a_k = (tid & 3) * 4;
    int w_k = tid >> 4, w_n = (tid & 15) * 4;

    float c[2][2][4] = {};

    cp16(&As[0][a_m][a_k], &g_pooled[(m0 + a_m)*FEAT + a_k]);
    cp16(&Ws[0][w_k][w_n], &Bk[w_k*H3 + n0 + w_n]);
    cpcommit();

    const int NIT = FEAT / 16;
    for (int it = 0; it < NIT; it++) {
        int nb = (it + 1) & 1;
        if (it + 1 < NIT) {
            int k0 = (it + 1) * 16;
            cp16(&As[nb][a_m][a_k], &g_pooled[(m0 + a_m)*FEAT + k0 + a_k]);
            cp16(&Ws[nb][w_k][w_n], &Bk[(k0 + w_k)*H3 + n0 + w_n]);
        }
        cpcommit();
        asm volatile("cp.async.wait_group 1;\n" ::);
        __syncthreads();
        int bf = it & 1;
        #pragma unroll
        for (int kh = 0; kh < 2; kh++) {
            int kk = kh * 8;
            unsigned a[2][4], b[2][2];
            #pragma unroll
            for (int mf = 0; mf < 2; mf++) {
                int m = wm + mf*16 + g;
                a[mf][0] = tf32r(As[bf][m    ][kk + tg]);
                a[mf][1] = tf32r(As[bf][m + 8][kk + tg]);
                a[mf][2] = tf32r(As[bf][m    ][kk + tg + 4]);
                a[mf][3] = tf32r(As[bf][m + 8][kk + tg + 4]);
            }
            #pragma unroll
            for (int nf = 0; nf < 2; nf++) {
                int n = wn + nf*8 + g;
                b[nf][0] = tf32r(Ws[bf][kk + tg    ][n]);
                b[nf][1] = tf32r(Ws[bf][kk + tg + 4][n]);
            }
            #pragma unroll
            for (int mf = 0; mf < 2; mf++)
                #pragma unroll
                for (int nf = 0; nf < 2; nf++)
                    mma8(c[mf][nf], a[mf], b[nf]);
        }
        __syncthreads();
    }

    #pragma unroll
    for (int mf = 0; mf < 2; mf++) {
        #pragma unroll
        for (int nf = 0; nf < 2; nf++) {
            int col = n0 + wn + nf*8 + tg*2;
            float bv0 = bias[col], bv1 = bias[col + 1];
            int r0 = m0 + wm + mf*16 + g;
            int b0 = r0 / TPOOL, t0 = r0 - b0*TPOOL;
            int r1 = r0 + 8;
            int b1 = r1 / TPOOL, t1 = r1 - b1*TPOOL;
            xp[(t0*H3 + col    )*NB + b0] = c[mf][nf][0] + bv0;
            xp[(t0*H3 + col + 1)*NB + b0] = c[mf][nf][1] + bv1;
            xp[(t1*H3 + col    )*NB + b1] = c[mf][nf][2] + bv0;
            xp[(t1*H3 + col + 1)*NB + b1] = c[mf][nf][3] + bv1;
        }
    }
}

/* ------- persistent GRU v4: 256 thr (no spills), rk in registers --------- */
__global__ void __launch_bounds__(256, 1) gru4_kernel(
    const float* __restrict__ rk_fw, const float* __restrict__ rk_bw,
    const float* __restrict__ b_fw,  const float* __restrict__ b_bw)
{
    extern __shared__ float smg[];
    float* hs  = smg;                 /* [320][64] tf32 bits, swizzled */
    float* pre = smg + PRE_OFF;       /* [2][64][66] fp32 partials */

    int bx = blockIdx.x, dir = bx >> 4, jb = bx & 15, j0 = jb * JPC;
    const float* rk = dir ? rk_bw : rk_fw;
    const float* br = (dir ? b_bw : b_fw) + H3;
    const float* xp = g_xp[dir];
    int tid = threadIdx.x, warp = tid >> 5, lane = tid & 31;
    int g = lane >> 2, tg = lane & 3;
    int nw  = (warp & 3) * 16;
    int khq = warp >> 2;              /* 0..1: K half of 160 */
    int kh  = khq * 160;

    for (int i = tid; i < HU*64; i += 256) {
        int k = i >> 6, c = i & 63;
        float v = 0.f;
        if (c < 60) {
            int gi = c / JPC, jj = c - gi*JPC;
            v = rk[k*H3 + gi*HU + j0 + jj];
        }
        hs[swz(k, c)] = __uint_as_float(tf32r(v));
    }
    __syncthreads();

    const unsigned* hsu = (const unsigned*)hs;
    unsigned Bf[20][2][2];
    #pragma unroll
    for (int ks = 0; ks < 20; ks++) {
        int kk = kh + ks*8;
        #pragma unroll
        for (int nf = 0; nf < 2; nf++) {
            int n = nw + nf*8 + g;
            Bf[ks][nf][0] = hsu[swz(kk + tg,     n)];
            Bf[ks][nf][1] = hsu[swz(kk + tg + 4, n)];
        }
    }
    __syncthreads();

    int b = tid & 63, jq = tid >> 6;  /* jq 0..3, 5 units each */
    float hold[5] = {0.f, 0.f, 0.f, 0.f, 0.f};
    float brz[5], brr[5], brh[5];
    #pragma unroll
    for (int i = 0; i < 5; i++) {
        int jg = j0 + jq + 4*i;
        brz[i] = br[jg]; brr[i] = br[HU + jg]; brh[i] = br[2*HU + jg];
    }

    float* buf0 = g_htf[dir][0];
    float* buf1 = g_htf[dir][1];

    float mzp[5], mrp[5], mhp[5];
    {
        int tt0 = dir ? (TPOOL - 1) : 0;
        #pragma unroll
        for (int i = 0; i < 5; i++) {
            int jg = j0 + jq + 4*i;
            mzp[i] = xp[(tt0*H3 + jg)*NB + b];
            mrp[i] = xp[(tt0*H3 + HU + jg)*NB + b];
            mhp[i] = xp[(tt0*H3 + 2*HU + jg)*NB + b];
        }
    }
    unsigned mygen = 0;

    for (int s = 0; s < TPOOL; s++) {
        int tt = dir ? (TPOOL - 1 - s) : s;

        if (s > 0) {
            if (tid == 0) {
                while (*((volatile unsigned*)&g_gen2[dir]) == mygen) { }
            }
            __syncthreads();

            const float4* src = (const float4*)((s & 1) ? buf0 : buf1);
            float4* hs4 = (float4*)hs;
            for (int i = tid; i < HU*64/4; i += 256)
                cp16(&hs4[i], &src[i]);
            cpcommit();
            cpwait0();
            __syncthreads();

            float c[4][2][4] = {};
            #pragma unroll
            for (int ks = 0; ks < 20; ks++) {
                int kk = kh + ks*8;
                unsigned a[4][4];
                #pragma unroll
                for (int mt = 0; mt < 4; mt++) {
                    int m = mt*16;
                    a[mt][0] = hsu[swz(kk + tg,     m + g)];
                    a[mt][1] = hsu[swz(kk + tg,     m + 8 + g)];
                    a[mt][2] = hsu[swz(kk + tg + 4, m + g)];
                    a[mt][3] = hsu[swz(kk + tg + 4, m + 8 + g)];
                }
                #pragma unroll
                for (int mt = 0; mt < 4; mt++)
                    #pragma unroll
                    for (int nf = 0; nf < 2; nf++)
                        mma8(c[mt][nf], a[mt], Bf[ks][nf]);
            }
            float* pb = pre + khq*64*66;
            #pragma unroll
            for (int mt = 0; mt < 4; mt++) {
                #pragma unroll
                for (int nf = 0; nf < 2; nf++) {
                    int n = nw + nf*8 + tg*2;
                    int m = mt*16 + g;
                    pb[(n    )*66 + m]     = c[mt][nf][0];
                    pb[(n + 1)*66 + m]     = c[mt][nf][1];
                    pb[(n    )*66 + m + 8] = c[mt][nf][2];
                    pb[(n + 1)*66 + m + 8] = c[mt][nf][3];
                }
            }
            __syncthreads();
        }

        float* wb = (s & 1) ? buf1 : buf0;
        #pragma unroll
        for (int i = 0; i < 5; i++) {
            int jl = jq + 4*i, jg = j0 + jl;
            float az = 0.f, ar = 0.f, ah = 0.f;
            if (s > 0) {
                az = pre[(jl        )*66 + b] + pre[64*66 + (jl        )*66 + b];
                ar = pre[(JPC + jl  )*66 + b] + pre[64*66 + (JPC + jl  )*66 + b];
                ah = pre[(2*JPC + jl)*66 + b] + pre[64*66 + (2*JPC + jl)*66 + b];
            }
            float z    = sigf(mzp[i] + az + brz[i]);
            float r    = sigf(mrp[i] + ar + brr[i]);
            float cand = tanhf(mhp[i] + r * (ah + brh[i]));
            float hn   = z * hold[i] + (1.f - z) * cand;
            hold[i] = hn;
            unsigned hb = tf32r(hn);
            g_y[((tt*2 + dir)*HU + jg)*NB + b] = __uint_as_float(hb);
            wb[swz(jg, b)] = __uint_as_float(hb);
        }

        if (s < TPOOL - 1) {
            __threadfence();
            __syncthreads();
            if (tid == 0) {
                mygen = *((volatile unsigned*)&g_gen2[dir]);
                if (atomicAdd(&g_cnt2[dir], 1u) == GB - 1u) {
                    g_cnt2[dir] = 0u;
                    __threadfence();
                    atomicAdd(&g_gen2[dir], 1u);
                }
            }
            int tn = dir ? (TPOOL - 2 - s) : (s + 1);
            #pragma unroll
            for (int i = 0; i < 5; i++) {
                int jg = j0 + jq + 4*i;
                mzp[i] = xp[(tn*H3 + jg)*NB + b];
                mrp[i] = xp[(tn*H3 + HU + jg)*NB + b];
                mhp[i] = xp[(tn*H3 + 2*HU + jg)*NB + b];
            }
        }
    }
}

/* -------- dense1 via tf32 MMA, depth-4 pipeline, KSPLIT=40 --------------- */
__global__ void __launch_bounds__(256) dense1_mma(const float* __restrict__ W)
{
    __shared__ __align__(16) float As[4][16][72];
    __shared__ __align__(16) float Ws[4][16][136];
    int n0 = blockIdx.x * 128;
    int kbeg = blockIdx.y * KSEG;
    int tid = threadIdx.x, warp = tid >> 5, lane = tid & 31;
    int g = lane >> 2, tg = lane & 3;
    int wm = (warp >> 2) * 32, wn = (warp & 3) * 32;

    int a_k = tid >> 4, a_m = (tid & 15) * 4;
    int w_k = tid >> 5, w_n = (tid & 31) * 4;
    bool wok = (n0 + w_n) < ND1;

    if (!wok) {
        #pragma unroll
        for (int bf = 0; bf < 4; bf++) {
            *(float4*)&Ws[bf][w_k    ][w_n] = make_float4(0,0,0,0);
            *(float4*)&Ws[bf][w_k + 8][w_n] = make_float4(0,0,0,0);
        }
    }

    float c[2][4][4] = {};

    const int NIT = KSEG / 16;   /* 75 */
    #pragma unroll
    for (int p = 0; p < 3; p++) {
        int k0 = kbeg + p*16;
        cp16(&As[p][a_k][a_m], &g_y[(k0 + a_k)*NB + a_m]);
        if (wok) {
            cp16(&Ws[p][w_k    ][w_n], &W[(size_t)(k0 + w_k    )*ND1 + n0 + w_n]);
            cp16(&Ws[p][w_k + 8][w_n], &W[(size_t)(k0 + w_k + 8)*ND1 + n0 + w_n]);
        }
        cpcommit();
    }

    for (int it = 0; it < NIT; it++) {
        if (it + 3 < NIT) {
            int p = (it + 3) & 3;
            int k0 = kbeg + (it + 3) * 16;
            cp16(&As[p][a_k][a_m], &g_y[(k0 + a_k)*NB + a_m]);
            if (wok) {
                cp16(&Ws[p][w_k    ][w_n], &W[(size_t)(k0 + w_k    )*ND1 + n0 + w_n]);
                cp16(&Ws[p][w_k + 8][w_n], &W[(size_t)(k0 + w_k + 8)*ND1 + n0 + w_n]);
            }
        }
        cpcommit();
        cpwait3();
        __syncthreads();
        int bf = it & 3;
        #pragma unroll
        for (int kh = 0; kh < 2; kh++) {
            int kk = kh * 8;
            unsigned a[2][4], b[4][2];
            #pragma unroll
            for (int mf = 0; mf < 2; mf++) {
                int m = wm + mf*16 + g;
                a[mf][0] = __float_as_uint(As[bf][kk + tg    ][m]);
                a[mf][1] = __float_as_uint(As[bf][kk + tg    ][m + 8]);
                a[mf][2] = __float_as_uint(As[bf][kk + tg + 4][m]);
                a[mf][3] = __float_as_uint(As[bf][kk + tg + 4][m + 8]);
            }
            #pragma unroll
            for (int nf = 0; nf < 4; nf++) {
                int n = wn + nf*8 + g;
                b[nf][0] = tf32r(Ws[bf][kk + tg    ][n]);
                b[nf][1] = tf32r(Ws[bf][kk + tg + 4][n]);
            }
            #pragma unroll
            for (int mf = 0; mf < 2; mf++)
                #pragma unroll
                for (int nf = 0; nf < 4; nf++)
                    mma8(c[mf][nf], a[mf], b[nf]);
        }
        __syncthreads();
    }

    float* dst = g_part[blockIdx.y];
    #pragma unroll
    for (int mf = 0; mf < 2; mf++) {
        #pragma unroll
        for (int nf = 0; nf < 4; nf++) {
            int col = n0 + wn + nf*8 + tg*2;
            if (col < ND1) {
                int r0 = wm + mf*16 + g;
                *(float2*)&dst[r0*ND1 + col]       = make_float2(c[mf][nf][0], c[mf][nf][1]);
                *(float2*)&dst[(r0 + 8)*ND1 + col] = make_float2(c[mf][nf][2], c[mf][nf][3]);
            }
        }
    }
}

__global__ void __launch_bounds__(256) reduce1_kernel(const float* __restrict__ b1)
{
    int i = blockIdx.x * 256 + threadIdx.x;
    if (i >= NB*ND1) return;
    int n = i % ND1;
    float s = b1[n];
    #pragma unroll
    for (int p = 0; p < KSPLIT; p++) s += g_part[p][i];
    g_hidden[i] = fmaxf(s, 0.f);
}

__global__ void __launch_bounds__(320) dense2_kernel(const float* __restrict__ w2,
                                                     const float* __restrict__ b2,
                                                     float* __restrict__ out)
{
    __shared__ float hsh[2*ND1];
    int m0 = blockIdx.x * 2, tid = threadIdx.x;
    for (int i = tid; i < 2*ND1; i += 320) hsh[i] = g_hidden[m0*ND1 + i];
    __syncthreads();
    if (tid >= ND2) return;
    float a0 = 0.f, a1 = 0.f, c0 = 0.f, c1 = 0.f;
    for (int k = 0; k < ND1; k += 2) {
        float w0 = w2[(k    )*ND2 + tid];
        float w1 = w2[(k + 1)*ND2 + tid];
        a0 = fmaf(hsh[k], w0, a0);       a1 = fmaf(hsh[k + 1], w1, a1);
        c0 = fmaf(hsh[ND1 + k], w0, c0); c1 = fmaf(hsh[ND1 + k + 1], w1, c1);
    }
    float bb = b2[tid];
    out[m0*ND2 + tid]       = sigf(a0 + a1 + bb);
    out[(m0 + 1)*ND2 + tid] = sigf(c0 + c1 + bb);
}

extern "C" void kernel_launch(void* const* d_in, const int* in_sizes, int n_in,
                              void* d_out, int out_size)
{
    const float* inputs = (const float*)d_in[0];
    const float* conv_w = (const float*)d_in[1];
    const float* conv_b = (const float*)d_in[2];
    const float* fw_k   = (const float*)d_in[3];
    const float* fw_rk  = (const float*)d_in[4];
    const float* fw_b   = (const float*)d_in[5];
    const float* bw_k   = (const float*)d_in[6];
    const float* bw_rk  = (const float*)d_in[7];
    const float* bw_b   = (const float*)d_in[8];
    const float* w1     = (const float*)d_in[9];
    const float* b1     = (const float*)d_in[10];
    const float* w2     = (const float*)d_in[11];
    const float* b2     = (const float*)d_in[12];
    float* out = (float*)d_out;

    cudaFuncSetAttribute(gru4_kernel, cudaFuncAttributeMaxDynamicSharedMemorySize, GRU4_SMEM);

    conv_mma<<<dim3(FEAT/64, NB), 256>>>(inputs, conv_w, conv_b);
    xproj_mma<<<dim3(TPOOL, H3/64, 2), 256>>>(fw_k, bw_k, fw_b, bw_b);
    gru4_kernel<<<2*GB, 256, GRU4_SMEM>>>(fw_rk, bw_rk, fw_b, bw_b);
    dense1_mma<<<dim3(16, KSPLIT), 256>>>(w1);
    reduce1_kernel<<<(NB*ND1 + 255)/256, 256>>>(b1);
    dense2_kernel<<<NB/2, 320>>>(w2, b2, out);
}